// round 9
// baseline (speedup 1.0000x reference)
#include <cuda_runtime.h>
#include <math.h>

#define BB   4
#define CCH  96
#define LL   4096
#define DI   192
#define DS   16
#define DTR  6
#define NTOK (BB*LL)      // 16384
#define NCH  256          // scan chunks per batch
#define CSZ  16           // chunk size
#define SUP  8            // super-chunks (32 chunks each)
#define ROWS (DI*DS)      // 3072

// ---------------- scratch ----------------
__device__ __align__(16) float g_xi_raw[NTOK*DI];
__device__ __align__(16) float g_z[NTOK*DI];
__device__ __align__(16) float g_xi[NTOK*DI];
__device__ __align__(16) float g_dt[NTOK*DI];
__device__ __align__(16) float g_Bm[NTOK*DS];
__device__ __align__(16) float g_Cm[NTOK*DS];
__device__ __align__(16) float g_dts[BB*NCH*DI];      // per-chunk dt sums
__device__ __align__(16) float g_hend[BB*NCH*ROWS];
__device__ __align__(16) float g_Hst[BB*NCH*ROWS];
__device__ __align__(16) float g_sP[BB*SUP*ROWS];
__device__ __align__(16) float g_sH[BB*SUP*ROWS];
__device__ __align__(16) float g_sS[BB*SUP*ROWS];
__device__ __align__(16) float g_ym[NTOK*DI];
__device__ __align__(16) float g_xm[BB*CCH*LL];

// ---------------- f32x2 helpers ----------------
__device__ __forceinline__ unsigned long long pack2(float lo, float hi) {
    unsigned long long r;
    asm("mov.b64 %0, {%1, %2};" : "=l"(r) : "f"(lo), "f"(hi));
    return r;
}
__device__ __forceinline__ void ffma2(unsigned long long &d, unsigned long long a, unsigned long long b) {
    asm("fma.rn.f32x2 %0, %1, %2, %3;" : "=l"(d) : "l"(a), "l"(b), "l"(d));
}
__device__ __forceinline__ float2 unpack2(unsigned long long v) {
    float2 f;
    asm("mov.b64 {%0, %1}, %2;" : "=f"(f.x), "=f"(f.y) : "l"(v));
    return f;
}
// Ep[s] = E^(s+1), log-depth tree
__device__ __forceinline__ void build_pows(float E, float* Ep) {
    Ep[0] = E;
#pragma unroll
    for (int s = 1; s < DS; s++) {
        int p = s + 1;
        Ep[s] = Ep[p/2 - 1] * Ep[p - p/2 - 1];
    }
}

// ======================================================================
// K1: in_proj GEMM (f32x2)
// ======================================================================
__global__ __launch_bounds__(256) void k_inproj(const float* __restrict__ x,
                                                const float* __restrict__ w) {
    __shared__ __align__(16) float As[48*64];
    __shared__ __align__(16) float Bs[48*66];
    int tid = threadIdx.x;
    int t0 = blockIdx.y * 64;
    int d0 = blockIdx.x * 64;
    int b  = t0 >> 12;
    int l0 = t0 & (LL-1);
    const float* xb = x + (size_t)b*CCH*LL + l0;

    int tx = tid & 15, ty = tid >> 4;
    unsigned long long acc[4][2];
#pragma unroll
    for (int i = 0; i < 4; i++) { acc[i][0] = 0ull; acc[i][1] = 0ull; }

    for (int ck = 0; ck < 2; ck++) {
        int cb = ck * 48;
        for (int li = tid; li < 48*64; li += 256) {
            int c = li >> 6, i = li & 63;
            As[c*64 + i] = xb[(size_t)(cb + c)*LL + i];
        }
        for (int li = tid; li < 64*48; li += 256) {
            int dl = li / 48, c = li - dl*48;
            Bs[c*66 + dl] = w[(d0 + dl)*CCH + cb + c];
        }
        __syncthreads();
#pragma unroll 8
        for (int c = 0; c < 48; c++) {
            float4 av = *(const float4*)&As[c*64 + ty*4];
            unsigned long long a0 = pack2(av.x, av.x);
            unsigned long long a1 = pack2(av.y, av.y);
            unsigned long long a2 = pack2(av.z, av.z);
            unsigned long long a3 = pack2(av.w, av.w);
            unsigned long long b01 = *(const unsigned long long*)&Bs[c*66 + tx*4];
            unsigned long long b23 = *(const unsigned long long*)&Bs[c*66 + tx*4 + 2];
            ffma2(acc[0][0], a0, b01); ffma2(acc[0][1], a0, b23);
            ffma2(acc[1][0], a1, b01); ffma2(acc[1][1], a1, b23);
            ffma2(acc[2][0], a2, b01); ffma2(acc[2][1], a2, b23);
            ffma2(acc[3][0], a3, b01); ffma2(acc[3][1], a3, b23);
        }
        __syncthreads();
    }
    float* dst; int dd;
    if (d0 < DI) { dst = g_xi_raw; dd = d0; } else { dst = g_z; dd = d0 - DI; }
#pragma unroll
    for (int i = 0; i < 4; i++) {
        int t = t0 + ty*4 + i;
        float2 lo = unpack2(acc[i][0]);
        float2 hi = unpack2(acc[i][1]);
        *(float4*)&dst[(size_t)t*DI + dd + tx*4] = make_float4(lo.x, lo.y, hi.x, hi.y);
    }
}

// ======================================================================
// K2a: depthwise causal conv1d + bias + SiLU (vectorized)
// ======================================================================
__global__ __launch_bounds__(256) void k_conv1d(const float* __restrict__ cw,
                                                const float* __restrict__ cb) {
    int gidx = blockIdx.x * 256 + threadIdx.x;
    int dvec = gidx % 48;
    int tg   = gidx / 48;
    int t0   = tg * 8;
    int l0   = t0 & (LL-1);
    int d4   = dvec * 4;

    float4 wk[4];
#pragma unroll
    for (int k = 0; k < 4; k++) {
        wk[k].x = cw[(d4+0)*4 + k];
        wk[k].y = cw[(d4+1)*4 + k];
        wk[k].z = cw[(d4+2)*4 + k];
        wk[k].w = cw[(d4+3)*4 + k];
    }
    float4 bias = *(const float4*)&cb[d4];

    float4 win[11];
#pragma unroll
    for (int j = 0; j < 11; j++) {
        int l = l0 - 3 + j;
        if (l >= 0)
            win[j] = *(const float4*)&g_xi_raw[(size_t)(t0 - 3 + j)*DI + d4];
        else
            win[j] = make_float4(0.f, 0.f, 0.f, 0.f);
    }

#pragma unroll
    for (int tt = 0; tt < 8; tt++) {
        float4 v = bias;
#pragma unroll
        for (int k = 0; k < 4; k++) {
            float4 u = win[tt + k];
            v.x += wk[k].x * u.x;
            v.y += wk[k].y * u.y;
            v.z += wk[k].z * u.z;
            v.w += wk[k].w * u.w;
        }
        v.x = v.x / (1.f + __expf(-v.x));
        v.y = v.y / (1.f + __expf(-v.y));
        v.z = v.z / (1.f + __expf(-v.z));
        v.w = v.w / (1.f + __expf(-v.w));
        *(float4*)&g_xi[(size_t)(t0 + tt)*DI + d4] = v;
    }
}

// ======================================================================
// K2b: x_dbl GEMM + dt proj (tiled)
// ======================================================================
__global__ __launch_bounds__(256) void k_xproj(const float* __restrict__ xpw,
                                               const float* __restrict__ dpw,
                                               const float* __restrict__ dpb) {
    __shared__ float As[64*49];
    __shared__ float Ws[48*48];
    __shared__ float Xd[64*42];
    __shared__ float Wd[DI*DTR + DI];
    int tid = threadIdx.x;
    int t0 = blockIdx.x * 64;
    int tx = tid & 15, ty = tid >> 4;

    for (int li = tid; li < DI*DTR; li += 256) Wd[li] = dpw[li];
    if (tid < DI) Wd[DI*DTR + tid] = dpb[tid];

    float acc[4][3];
#pragma unroll
    for (int i = 0; i < 4; i++)
#pragma unroll
        for (int j = 0; j < 3; j++) acc[i][j] = 0.f;

    for (int kc = 0; kc < 4; kc++) {
        int c0 = kc * 48;
        for (int li = tid; li < 64*48; li += 256) {
            int tk = li / 48, c = li - tk*48;
            As[tk*49 + c] = g_xi[(size_t)(t0 + tk)*DI + c0 + c];
        }
        for (int li = tid; li < 48*48; li += 256) {
            int j = li / 48, c = li - j*48;
            Ws[li] = (j < 38) ? xpw[j*DI + c0 + c] : 0.f;
        }
        __syncthreads();
#pragma unroll 8
        for (int c = 0; c < 48; c++) {
            float a0 = As[(tx*4 + 0)*49 + c];
            float a1 = As[(tx*4 + 1)*49 + c];
            float a2 = As[(tx*4 + 2)*49 + c];
            float a3 = As[(tx*4 + 3)*49 + c];
            float w0 = Ws[(ty*3 + 0)*48 + c];
            float w1 = Ws[(ty*3 + 1)*48 + c];
            float w2 = Ws[(ty*3 + 2)*48 + c];
            acc[0][0] += a0*w0; acc[0][1] += a0*w1; acc[0][2] += a0*w2;
            acc[1][0] += a1*w0; acc[1][1] += a1*w1; acc[1][2] += a1*w2;
            acc[2][0] += a2*w0; acc[2][1] += a2*w1; acc[2][2] += a2*w2;
            acc[3][0] += a3*w0; acc[3][1] += a3*w1; acc[3][2] += a3*w2;
        }
        __syncthreads();
    }

#pragma unroll
    for (int i = 0; i < 4; i++)
#pragma unroll
        for (int jj = 0; jj < 3; jj++) {
            int j = ty*3 + jj;
            if (j < 38) Xd[(tx*4 + i)*42 + j] = acc[i][jj];
        }
    __syncthreads();

    for (int li = tid; li < 64*DS; li += 256) {
        int t = li >> 4, s = li & 15;
        g_Bm[(size_t)(t0 + t)*DS + s] = Xd[t*42 + DTR + s];
        g_Cm[(size_t)(t0 + t)*DS + s] = Xd[t*42 + DTR + DS + s];
    }
    for (int idx = tid; idx < 64*DI; idx += 256) {
        int tl2 = idx / DI;
        int d = idx - tl2*DI;
        float a = Wd[DI*DTR + d];
#pragma unroll
        for (int r = 0; r < DTR; r++) a += Xd[tl2*42 + r] * Wd[d*DTR + r];
        float sp = fmaxf(a, 0.f) + log1pf(__expf(-fabsf(a)));
        g_dt[(size_t)(t0 + tl2)*DI + d] = sp;
    }
}

// ======================================================================
// K3: scan pass A — local chunk scan, pipelined; stores h_end + dtsum.
// ======================================================================
__global__ __launch_bounds__(DI) void k_scanA(const float* __restrict__ A_log) {
    __shared__ float Bs[CSZ*DS];
    int d  = threadIdx.x;
    int b  = blockIdx.x >> 8;
    int ch = blockIdx.x & (NCH-1);
    int l0 = ch * CSZ;
    for (int li = d; li < CSZ*DS; li += DI)
        Bs[li] = g_Bm[(size_t)(b*LL + l0)*DS + li];
    __syncthreads();

    float Ad[DS], h[DS];
#pragma unroll
    for (int s = 0; s < DS; s++) { Ad[s] = -__expf(A_log[d*DS + s]); h[s] = 0.f; }
    float Ad0 = Ad[0];
    bool fast = true;
#pragma unroll
    for (int s = 1; s < DS; s++)
        fast = fast && (fabsf(Ad[s] - (s+1)*Ad0) <= 1e-4f * (float)(s+1) * fabsf(Ad0));

    float dtsum = 0.f;
    const float* dtp = g_dt + (size_t)(b*LL + l0)*DI + d;
    const float* xip = g_xi + (size_t)(b*LL + l0)*DI + d;

    float dtv = dtp[0];
    float xiv = xip[0];
    if (fast) {
#pragma unroll
        for (int t = 0; t < CSZ; t++) {
            float dtn = 0.f, xin = 0.f;
            if (t < CSZ-1) {
                dtn = dtp[(size_t)(t+1)*DI];
                xin = xip[(size_t)(t+1)*DI];
            }
            dtsum += dtv;
            float dx = dtv * xiv;
            float Ep[DS];
            build_pows(__expf(Ad0*dtv), Ep);
#pragma unroll
            for (int s = 0; s < DS; s++)
                h[s] = Ep[s] * h[s] + dx * Bs[t*DS + s];
            dtv = dtn; xiv = xin;
        }
    } else {
#pragma unroll
        for (int t = 0; t < CSZ; t++) {
            float dtn = 0.f, xin = 0.f;
            if (t < CSZ-1) {
                dtn = dtp[(size_t)(t+1)*DI];
                xin = xip[(size_t)(t+1)*DI];
            }
            dtsum += dtv;
            float dx = dtv * xiv;
#pragma unroll
            for (int s = 0; s < DS; s++)
                h[s] = __expf(Ad[s]*dtv) * h[s] + dx * Bs[t*DS + s];
            dtv = dtn; xiv = xin;
        }
    }
    size_t base = ((size_t)(b*NCH + ch)*DI + d)*DS;
    float4* pe = (float4*)(g_hend + base);
#pragma unroll
    for (int q = 0; q < 4; q++)
        pe[q] = make_float4(h[4*q], h[4*q+1], h[4*q+2], h[4*q+3]);
    g_dts[(size_t)(b*NCH + ch)*DI + d] = dtsum;
}

// ======================================================================
// K4a/b/c: parallel chunk combine.  P reconstructed as exp(Ad*dtsum).
// ======================================================================
__global__ __launch_bounds__(256) void k_scanB1(const float* __restrict__ A_log) {
    int r0 = blockIdx.x * 256 + threadIdx.x;   // row = d*DS + s
    int sc = blockIdx.y, b = blockIdx.z;
    float Ad = -__expf(A_log[r0]);
    int dd = r0 >> 4;
    size_t bh = ((size_t)(b*NCH) + sc*32)*ROWS + r0;
    size_t bd = ((size_t)(b*NCH) + sc*32)*DI + dd;
    float a = 1.f, bb = 0.f;
    float ds = g_dts[bd], hv = g_hend[bh];
#pragma unroll 4
    for (int c = 0; c < 32; c++) {
        float dsn = 0.f, hn = 0.f;
        if (c < 31) {
            dsn = g_dts[bd + (size_t)(c+1)*DI];
            hn  = g_hend[bh + (size_t)(c+1)*ROWS];
        }
        float P = __expf(Ad*ds);
        a = P*a;
        bb = P*bb + hv;
        ds = dsn; hv = hn;
    }
    size_t so = ((size_t)b*SUP + sc)*ROWS + r0;
    g_sP[so] = a;
    g_sH[so] = bb;
}

__global__ __launch_bounds__(256) void k_scanB2() {
    int idx = blockIdx.x * 256 + threadIdx.x;
    int b = idx / ROWS;
    int r = idx - b*ROWS;
    float H = 0.f;
#pragma unroll
    for (int sc = 0; sc < SUP; sc++) {
        size_t ofs = ((size_t)b*SUP + sc)*ROWS + r;
        g_sS[ofs] = H;
        H = g_sP[ofs]*H + g_sH[ofs];
    }
}

__global__ __launch_bounds__(256) void k_scanB3(const float* __restrict__ A_log) {
    int r0 = blockIdx.x * 256 + threadIdx.x;
    int sc = blockIdx.y, b = blockIdx.z;
    float Ad = -__expf(A_log[r0]);
    int dd = r0 >> 4;
    float H = g_sS[((size_t)b*SUP + sc)*ROWS + r0];
    size_t bh = ((size_t)(b*NCH) + sc*32)*ROWS + r0;
    size_t bd = ((size_t)(b*NCH) + sc*32)*DI + dd;
    float ds = g_dts[bd], hv = g_hend[bh];
#pragma unroll 4
    for (int c = 0; c < 32; c++) {
        float dsn = 0.f, hn = 0.f;
        if (c < 31) {
            dsn = g_dts[bd + (size_t)(c+1)*DI];
            hn  = g_hend[bh + (size_t)(c+1)*ROWS];
        }
        g_Hst[bh + (size_t)c*ROWS] = H;
        float P = __expf(Ad*ds);
        H = P*H + hv;
        ds = dsn; hv = hn;
    }
}

// ======================================================================
// K5: scan pass C — seeded re-scan + fused skip/gate, pipelined loads.
// ======================================================================
__global__ __launch_bounds__(DI) void k_scanC(const float* __restrict__ A_log,
                                              const float* __restrict__ Dp) {
    __shared__ float Bs[CSZ*DS];
    __shared__ float Cs[CSZ*DS];
    int d  = threadIdx.x;
    int b  = blockIdx.x >> 8;
    int ch = blockIdx.x & (NCH-1);
    int l0 = ch * CSZ;
    for (int li = d; li < CSZ*DS; li += DI) {
        Bs[li] = g_Bm[(size_t)(b*LL + l0)*DS + li];
        Cs[li] = g_Cm[(size_t)(b*LL + l0)*DS + li];
    }
    __syncthreads();

    float Ad[DS], h[DS];
#pragma unroll
    for (int s = 0; s < DS; s++) Ad[s] = -__expf(A_log[d*DS + s]);
    float Ad0 = Ad[0];
    bool fast = true;
#pragma unroll
    for (int s = 1; s < DS; s++)
        fast = fast && (fabsf(Ad[s] - (s+1)*Ad0) <= 1e-4f * (float)(s+1) * fabsf(Ad0));

    size_t hbase = ((size_t)(b*NCH + ch)*DI + d)*DS;
    const float4* hs = (const float4*)(g_Hst + hbase);
#pragma unroll
    for (int q = 0; q < 4; q++) {
        float4 v = hs[q];
        h[4*q] = v.x; h[4*q+1] = v.y; h[4*q+2] = v.z; h[4*q+3] = v.w;
    }
    float Dd = Dp[d];
    const float* dtp = g_dt + (size_t)(b*LL + l0)*DI + d;
    const float* xip = g_xi + (size_t)(b*LL + l0)*DI + d;
    const float* zp  = g_z  + (size_t)(b*LL + l0)*DI + d;
    float* outp      = g_ym + (size_t)(b*LL + l0)*DI + d;

    float dtv = dtp[0];
    float xiv = xip[0];
    float zv  = zp[0];
    if (fast) {
#pragma unroll
        for (int t = 0; t < CSZ; t++) {
            float dtn = 0.f, xin = 0.f, zn = 0.f;
            if (t < CSZ-1) {
                dtn = dtp[(size_t)(t+1)*DI];
                xin = xip[(size_t)(t+1)*DI];
                zn  = zp[(size_t)(t+1)*DI];
            }
            float dx = dtv * xiv;
            float Ep[DS];
            build_pows(__expf(Ad0*dtv), Ep);
            float y = 0.f;
#pragma unroll
            for (int s = 0; s < DS; s++) {
                h[s] = Ep[s]*h[s] + dx * Bs[t*DS + s];
                y += h[s] * Cs[t*DS + s];
            }
            float sz = zv / (1.f + __expf(-zv));
            outp[(size_t)t*DI] = (y + xiv*Dd) * sz;
            dtv = dtn; xiv = xin; zv = zn;
        }
    } else {
#pragma unroll
        for (int t = 0; t < CSZ; t++) {
            float dtn = 0.f, xin = 0.f, zn = 0.f;
            if (t < CSZ-1) {
                dtn = dtp[(size_t)(t+1)*DI];
                xin = xip[(size_t)(t+1)*DI];
                zn  = zp[(size_t)(t+1)*DI];
            }
            float dx = dtv * xiv;
            float y = 0.f;
#pragma unroll
            for (int s = 0; s < DS; s++) {
                h[s] = __expf(Ad[s]*dtv)*h[s] + dx * Bs[t*DS + s];
                y += h[s] * Cs[t*DS + s];
            }
            float sz = zv / (1.f + __expf(-zv));
            outp[(size_t)t*DI] = (y + xiv*Dd) * sz;
            dtv = dtn; xiv = xin; zv = zn;
        }
    }
}

// ======================================================================
// K6: out_proj GEMM (f32x2) -> [B, C, L]
// ======================================================================
__global__ __launch_bounds__(256) void k_outproj(const float* __restrict__ w) {
    __shared__ __align__(16) float As[64*66];
    __shared__ float Ws[64*49];
    int tid = threadIdx.x;
    int t0 = blockIdx.y * 64;
    int o0 = blockIdx.x * 48;
    int b  = t0 >> 12;
    int l0 = t0 & (LL-1);
    int tx = tid & 15, ty = tid >> 4;

    unsigned long long acc[2][3];
#pragma unroll
    for (int i = 0; i < 2; i++)
#pragma unroll
        for (int j = 0; j < 3; j++) acc[i][j] = 0ull;

    for (int ck = 0; ck < 3; ck++) {
        int c0 = ck * 64;
        for (int li = tid; li < 64*64; li += 256) {
            int tl = li >> 6, c = li & 63;
            As[c*66 + tl] = g_ym[(size_t)(t0 + tl)*DI + c0 + c];
        }
        for (int li = tid; li < 48*64; li += 256) {
            int ol = li >> 6, c = li & 63;
            Ws[c*49 + ol] = w[(o0 + ol)*DI + c0 + c];
        }
        __syncthreads();
#pragma unroll 8
        for (int c = 0; c < 64; c++) {
            unsigned long long a01 = *(const unsigned long long*)&As[c*66 + tx*4];
            unsigned long long a23 = *(const unsigned long long*)&As[c*66 + tx*4 + 2];
            float b0 = Ws[c*49 + ty*3 + 0];
            float b1 = Ws[c*49 + ty*3 + 1];
            float b2 = Ws[c*49 + ty*3 + 2];
            unsigned long long bd0 = pack2(b0, b0);
            unsigned long long bd1 = pack2(b1, b1);
            unsigned long long bd2 = pack2(b2, b2);
            ffma2(acc[0][0], a01, bd0); ffma2(acc[1][0], a23, bd0);
            ffma2(acc[0][1], a01, bd1); ffma2(acc[1][1], a23, bd1);
            ffma2(acc[0][2], a01, bd2); ffma2(acc[1][2], a23, bd2);
        }
        __syncthreads();
    }
#pragma unroll
    for (int j = 0; j < 3; j++) {
        int d = o0 + ty*3 + j;
        float2 lo = unpack2(acc[0][j]);
        float2 hi = unpack2(acc[1][j]);
        *(float4*)&g_xm[(size_t)(b*CCH + d)*LL + l0 + tx*4] = make_float4(lo.x, lo.y, hi.x, hi.y);
    }
}

// ======================================================================
// K7: 3x3 conv + BN + ReLU6 fused (R7 FMA-bound tiling).
// Block: 256 thr; tile = 4co x 16y x 64x; thread = 2co x 8px.
// ci chunks of 4; grid (24, 4, 4).
// ======================================================================
__global__ __launch_bounds__(256) void k_conv2d(const float* __restrict__ w,
                         const float* __restrict__ bng, const float* __restrict__ bnb,
                         const float* __restrict__ bnm, const float* __restrict__ bnv,
                         float* __restrict__ out) {
    __shared__ float in_s[4*18*66];              // 19.0 KB
    __shared__ __align__(8) float2 w2_s[4*9*4];  // 1.2 KB
    int tid = threadIdx.x;
    int co0 = blockIdx.x * 4;
    int y0  = blockIdx.y * 16;
    int b   = blockIdx.z;
    int cg = tid >> 7;            // 0..1 -> co pair cg*2
    int r  = tid & 127;
    int ty = r >> 3;              // 0..15
    int xg = r & 7;               // 0..7 -> x = xg*8

    // zero x-halo columns once (cols 0 and 65 always outside)
    for (int li = tid; li < 4*18*2; li += 256) {
        int rowid = li >> 1, side = li & 1;
        in_s[rowid*66 + (side ? 65 : 0)] = 0.f;
    }

    unsigned long long acc[2][4];
#pragma unroll
    for (int co = 0; co < 2; co++)
#pragma unroll
        for (int q = 0; q < 4; q++) acc[co][q] = 0ull;

    for (int cc = 0; cc < 24; cc++) {
        int ci0 = cc * 4;
        __syncthreads();
        for (int li = tid; li < 288; li += 256) {
            int rowid = li >> 2, q = li & 3;
            int ci = rowid / 18, rr = rowid - ci*18;
            int gy = y0 - 1 + rr;
            float4 v0, v1, v2, v3;
            if (gy >= 0 && gy < 64) {
                const float4* src = (const float4*)&g_xm[(((size_t)(b*CCH + ci0 + ci)*64 + gy)*64) + q*16];
                v0 = src[0]; v1 = src[1]; v2 = src[2]; v3 = src[3];
            } else {
                v0 = v1 = v2 = v3 = make_float4(0.f,0.f,0.f,0.f);
            }
            float* dstp = in_s + (ci*18 + rr)*66 + 1 + q*16;
            dstp[0]=v0.x;  dstp[1]=v0.y;  dstp[2]=v0.z;  dstp[3]=v0.w;
            dstp[4]=v1.x;  dstp[5]=v1.y;  dstp[6]=v1.z;  dstp[7]=v1.w;
            dstp[8]=v2.x;  dstp[9]=v2.y;  dstp[10]=v2.z; dstp[11]=v2.w;
            dstp[12]=v3.x; dstp[13]=v3.y; dstp[14]=v3.z; dstp[15]=v3.w;
        }
        if (tid < 144) {
            int ci = tid / 36, rem = tid - ci*36;
            int k = rem >> 2, co = rem & 3;
            float wv = w[((co0 + co)*CCH + ci0 + ci)*9 + k];
            w2_s[(ci*9 + k)*4 + co] = make_float2(wv, wv);
        }
        __syncthreads();

        const unsigned long long* wsp = (const unsigned long long*)w2_s;
#pragma unroll
        for (int ci = 0; ci < 4; ci++) {
#pragma unroll
            for (int ky = 0; ky < 3; ky++) {
                const unsigned long long* row =
                    (const unsigned long long*)(in_s + (ci*18 + ty + ky)*66 + xg*8);
                unsigned long long u0 = row[0], u1 = row[1], u2 = row[2],
                                   u3 = row[3], u4 = row[4];
                float2 f0 = unpack2(u0), f1 = unpack2(u1), f2 = unpack2(u2),
                       f3 = unpack2(u3), f4 = unpack2(u4);
                unsigned long long p0 = pack2(f0.y, f1.x);
                unsigned long long p1 = pack2(f1.y, f2.x);
                unsigned long long p2 = pack2(f2.y, f3.x);
                unsigned long long p3 = pack2(f3.y, f4.x);
                const unsigned long long* wb = wsp + (size_t)(ci*9 + ky*3)*4 + cg*2;
#pragma unroll
                for (int co = 0; co < 2; co++) {
                    unsigned long long w0 = wb[co];
                    unsigned long long w1 = wb[4 + co];
                    unsigned long long w2v = wb[8 + co];
                    ffma2(acc[co][0], u0, w0); ffma2(acc[co][1], u1, w0);
                    ffma2(acc[co][2], u2, w0); ffma2(acc[co][3], u3, w0);
                    ffma2(acc[co][0], p0, w1); ffma2(acc[co][1], p1, w1);
                    ffma2(acc[co][2], p2, w1); ffma2(acc[co][3], p3, w1);
                    ffma2(acc[co][0], u1, w2v); ffma2(acc[co][1], u2, w2v);
                    ffma2(acc[co][2], u3, w2v); ffma2(acc[co][3], u4, w2v);
                }
            }
        }
    }

#pragma unroll
    for (int co = 0; co < 2; co++) {
        int c = co0 + cg*2 + co;
        float inv = bng[c] * rsqrtf(bnv[c] + 1e-5f);
        float sh  = bnb[c] - bnm[c]*inv;
        float2 a0 = unpack2(acc[co][0]);
        float2 a1 = unpack2(acc[co][1]);
        float2 a2 = unpack2(acc[co][2]);
        float2 a3 = unpack2(acc[co][3]);
        float4 o0, o1;
        o0.x = fminf(fmaxf(a0.x*inv + sh, 0.f), 6.f);
        o0.y = fminf(fmaxf(a0.y*inv + sh, 0.f), 6.f);
        o0.z = fminf(fmaxf(a1.x*inv + sh, 0.f), 6.f);
        o0.w = fminf(fmaxf(a1.y*inv + sh, 0.f), 6.f);
        o1.x = fminf(fmaxf(a2.x*inv + sh, 0.f), 6.f);
        o1.y = fminf(fmaxf(a2.y*inv + sh, 0.f), 6.f);
        o1.z = fminf(fmaxf(a3.x*inv + sh, 0.f), 6.f);
        o1.w = fminf(fmaxf(a3.y*inv + sh, 0.f), 6.f);
        float* dst = &out[((size_t)(b*CCH + c)*64 + y0 + ty)*64 + xg*8];
        *(float4*)dst = o0;
        *(float4*)(dst + 4) = o1;
    }
}

// ======================================================================
extern "C" void kernel_launch(void* const* d_in, const int* in_sizes, int n_in,
                              void* d_out, int out_size) {
    const float* x         = (const float*)d_in[0];
    const float* in_proj_w = (const float*)d_in[1];
    const float* conv1d_w  = (const float*)d_in[2];
    const float* conv1d_b  = (const float*)d_in[3];
    const float* x_proj_w  = (const float*)d_in[4];
    const float* dt_proj_w = (const float*)d_in[5];
    const float* dt_proj_b = (const float*)d_in[6];
    const float* A_log     = (const float*)d_in[7];
    const float* Dp        = (const float*)d_in[8];
    const float* out_proj_w= (const float*)d_in[9];
    const float* conv2d_w  = (const float*)d_in[10];
    const float* bn_g      = (const float*)d_in[11];
    const float* bn_b      = (const float*)d_in[12];
    const float* bn_m      = (const float*)d_in[13];
    const float* bn_v      = (const float*)d_in[14];
    float* out = (float*)d_out;

    k_inproj <<<dim3(6, 256), 256>>>(x, in_proj_w);
    k_conv1d <<<(NTOK/8)*48/256, 256>>>(conv1d_w, conv1d_b);
    k_xproj  <<<NTOK/64, 256>>>(x_proj_w, dt_proj_w, dt_proj_b);
    k_scanA  <<<BB*NCH, DI>>>(A_log);
    k_scanB1 <<<dim3(12, SUP, BB), 256>>>(A_log);
    k_scanB2 <<<BB*ROWS/256, 256>>>();
    k_scanB3 <<<dim3(12, SUP, BB), 256>>>(A_log);
    k_scanC  <<<BB*NCH, DI>>>(A_log, Dp);
    k_outproj<<<dim3(2, 256), 256>>>(out_proj_w);
    k_conv2d <<<dim3(24, 4, 4), 256>>>(conv2d_w, bn_g, bn_b, bn_m, bn_v, out);
}

// round 10
// speedup vs baseline: 1.0536x; 1.0536x over previous
#include <cuda_runtime.h>
#include <math.h>

#define BB   4
#define CCH  96
#define LL   4096
#define DI   192
#define DS   16
#define DTR  6
#define NTOK (BB*LL)      // 16384
#define NCH  256          // scan chunks per batch
#define CSZ  16           // chunk size
#define SUP  8            // super-chunks (32 chunks each)
#define ROWS (DI*DS)      // 3072

// ---------------- scratch ----------------
__device__ __align__(16) float g_xi_raw[NTOK*DI];
__device__ __align__(16) float g_z[NTOK*DI];
__device__ __align__(16) float g_xi[NTOK*DI];
__device__ __align__(16) float g_dt[NTOK*DI];
__device__ __align__(16) float g_Bm[NTOK*DS];
__device__ __align__(16) float g_Cm[NTOK*DS];
__device__ __align__(16) float g_dts[BB*NCH*DI];      // per-chunk dt sums
__device__ __align__(16) float g_hend[BB*NCH*ROWS];
__device__ __align__(16) float g_Hst[BB*NCH*ROWS];
__device__ __align__(16) float g_sP[BB*SUP*ROWS];
__device__ __align__(16) float g_sH[BB*SUP*ROWS];
__device__ __align__(16) float g_sS[BB*SUP*ROWS];
__device__ __align__(16) float g_ym[NTOK*DI];
__device__ __align__(16) float g_xm[BB*CCH*LL];

// ---------------- f32x2 helpers ----------------
__device__ __forceinline__ unsigned long long pack2(float lo, float hi) {
    unsigned long long r;
    asm("mov.b64 %0, {%1, %2};" : "=l"(r) : "f"(lo), "f"(hi));
    return r;
}
__device__ __forceinline__ void ffma2(unsigned long long &d, unsigned long long a, unsigned long long b) {
    asm("fma.rn.f32x2 %0, %1, %2, %3;" : "=l"(d) : "l"(a), "l"(b), "l"(d));
}
__device__ __forceinline__ float2 unpack2(unsigned long long v) {
    float2 f;
    asm("mov.b64 {%0, %1}, %2;" : "=f"(f.x), "=f"(f.y) : "l"(v));
    return f;
}
// Ep[s] = E^(s+1), log-depth tree
__device__ __forceinline__ void build_pows(float E, float* Ep) {
    Ep[0] = E;
#pragma unroll
    for (int s = 1; s < DS; s++) {
        int p = s + 1;
        Ep[s] = Ep[p/2 - 1] * Ep[p - p/2 - 1];
    }
}

// ======================================================================
// K1: in_proj GEMM (f32x2)
// ======================================================================
__global__ __launch_bounds__(256) void k_inproj(const float* __restrict__ x,
                                                const float* __restrict__ w) {
    __shared__ __align__(16) float As[48*64];
    __shared__ __align__(16) float Bs[48*66];
    int tid = threadIdx.x;
    int t0 = blockIdx.y * 64;
    int d0 = blockIdx.x * 64;
    int b  = t0 >> 12;
    int l0 = t0 & (LL-1);
    const float* xb = x + (size_t)b*CCH*LL + l0;

    int tx = tid & 15, ty = tid >> 4;
    unsigned long long acc[4][2];
#pragma unroll
    for (int i = 0; i < 4; i++) { acc[i][0] = 0ull; acc[i][1] = 0ull; }

    for (int ck = 0; ck < 2; ck++) {
        int cb = ck * 48;
        for (int li = tid; li < 48*64; li += 256) {
            int c = li >> 6, i = li & 63;
            As[c*64 + i] = xb[(size_t)(cb + c)*LL + i];
        }
        for (int li = tid; li < 64*48; li += 256) {
            int dl = li / 48, c = li - dl*48;
            Bs[c*66 + dl] = w[(d0 + dl)*CCH + cb + c];
        }
        __syncthreads();
#pragma unroll 8
        for (int c = 0; c < 48; c++) {
            float4 av = *(const float4*)&As[c*64 + ty*4];
            unsigned long long a0 = pack2(av.x, av.x);
            unsigned long long a1 = pack2(av.y, av.y);
            unsigned long long a2 = pack2(av.z, av.z);
            unsigned long long a3 = pack2(av.w, av.w);
            unsigned long long b01 = *(const unsigned long long*)&Bs[c*66 + tx*4];
            unsigned long long b23 = *(const unsigned long long*)&Bs[c*66 + tx*4 + 2];
            ffma2(acc[0][0], a0, b01); ffma2(acc[0][1], a0, b23);
            ffma2(acc[1][0], a1, b01); ffma2(acc[1][1], a1, b23);
            ffma2(acc[2][0], a2, b01); ffma2(acc[2][1], a2, b23);
            ffma2(acc[3][0], a3, b01); ffma2(acc[3][1], a3, b23);
        }
        __syncthreads();
    }
    float* dst; int dd;
    if (d0 < DI) { dst = g_xi_raw; dd = d0; } else { dst = g_z; dd = d0 - DI; }
#pragma unroll
    for (int i = 0; i < 4; i++) {
        int t = t0 + ty*4 + i;
        float2 lo = unpack2(acc[i][0]);
        float2 hi = unpack2(acc[i][1]);
        *(float4*)&dst[(size_t)t*DI + dd + tx*4] = make_float4(lo.x, lo.y, hi.x, hi.y);
    }
}

// ======================================================================
// K2a: depthwise causal conv1d + bias + SiLU (vectorized)
// ======================================================================
__global__ __launch_bounds__(256) void k_conv1d(const float* __restrict__ cw,
                                                const float* __restrict__ cb) {
    int gidx = blockIdx.x * 256 + threadIdx.x;
    int dvec = gidx % 48;
    int tg   = gidx / 48;
    int t0   = tg * 8;
    int l0   = t0 & (LL-1);
    int d4   = dvec * 4;

    float4 wk[4];
#pragma unroll
    for (int k = 0; k < 4; k++) {
        wk[k].x = cw[(d4+0)*4 + k];
        wk[k].y = cw[(d4+1)*4 + k];
        wk[k].z = cw[(d4+2)*4 + k];
        wk[k].w = cw[(d4+3)*4 + k];
    }
    float4 bias = *(const float4*)&cb[d4];

    float4 win[11];
#pragma unroll
    for (int j = 0; j < 11; j++) {
        int l = l0 - 3 + j;
        if (l >= 0)
            win[j] = *(const float4*)&g_xi_raw[(size_t)(t0 - 3 + j)*DI + d4];
        else
            win[j] = make_float4(0.f, 0.f, 0.f, 0.f);
    }

#pragma unroll
    for (int tt = 0; tt < 8; tt++) {
        float4 v = bias;
#pragma unroll
        for (int k = 0; k < 4; k++) {
            float4 u = win[tt + k];
            v.x += wk[k].x * u.x;
            v.y += wk[k].y * u.y;
            v.z += wk[k].z * u.z;
            v.w += wk[k].w * u.w;
        }
        v.x = v.x / (1.f + __expf(-v.x));
        v.y = v.y / (1.f + __expf(-v.y));
        v.z = v.z / (1.f + __expf(-v.z));
        v.w = v.w / (1.f + __expf(-v.w));
        *(float4*)&g_xi[(size_t)(t0 + tt)*DI + d4] = v;
    }
}

// ======================================================================
// K2b: x_dbl GEMM + dt proj (tiled)
// ======================================================================
__global__ __launch_bounds__(256) void k_xproj(const float* __restrict__ xpw,
                                               const float* __restrict__ dpw,
                                               const float* __restrict__ dpb) {
    __shared__ float As[64*49];
    __shared__ float Ws[48*48];
    __shared__ float Xd[64*42];
    __shared__ float Wd[DI*DTR + DI];
    int tid = threadIdx.x;
    int t0 = blockIdx.x * 64;
    int tx = tid & 15, ty = tid >> 4;

    for (int li = tid; li < DI*DTR; li += 256) Wd[li] = dpw[li];
    if (tid < DI) Wd[DI*DTR + tid] = dpb[tid];

    float acc[4][3];
#pragma unroll
    for (int i = 0; i < 4; i++)
#pragma unroll
        for (int j = 0; j < 3; j++) acc[i][j] = 0.f;

    for (int kc = 0; kc < 4; kc++) {
        int c0 = kc * 48;
        for (int li = tid; li < 64*48; li += 256) {
            int tk = li / 48, c = li - tk*48;
            As[tk*49 + c] = g_xi[(size_t)(t0 + tk)*DI + c0 + c];
        }
        for (int li = tid; li < 48*48; li += 256) {
            int j = li / 48, c = li - j*48;
            Ws[li] = (j < 38) ? xpw[j*DI + c0 + c] : 0.f;
        }
        __syncthreads();
#pragma unroll 8
        for (int c = 0; c < 48; c++) {
            float a0 = As[(tx*4 + 0)*49 + c];
            float a1 = As[(tx*4 + 1)*49 + c];
            float a2 = As[(tx*4 + 2)*49 + c];
            float a3 = As[(tx*4 + 3)*49 + c];
            float w0 = Ws[(ty*3 + 0)*48 + c];
            float w1 = Ws[(ty*3 + 1)*48 + c];
            float w2 = Ws[(ty*3 + 2)*48 + c];
            acc[0][0] += a0*w0; acc[0][1] += a0*w1; acc[0][2] += a0*w2;
            acc[1][0] += a1*w0; acc[1][1] += a1*w1; acc[1][2] += a1*w2;
            acc[2][0] += a2*w0; acc[2][1] += a2*w1; acc[2][2] += a2*w2;
            acc[3][0] += a3*w0; acc[3][1] += a3*w1; acc[3][2] += a3*w2;
        }
        __syncthreads();
    }

#pragma unroll
    for (int i = 0; i < 4; i++)
#pragma unroll
        for (int jj = 0; jj < 3; jj++) {
            int j = ty*3 + jj;
            if (j < 38) Xd[(tx*4 + i)*42 + j] = acc[i][jj];
        }
    __syncthreads();

    for (int li = tid; li < 64*DS; li += 256) {
        int t = li >> 4, s = li & 15;
        g_Bm[(size_t)(t0 + t)*DS + s] = Xd[t*42 + DTR + s];
        g_Cm[(size_t)(t0 + t)*DS + s] = Xd[t*42 + DTR + DS + s];
    }
    for (int idx = tid; idx < 64*DI; idx += 256) {
        int tl2 = idx / DI;
        int d = idx - tl2*DI;
        float a = Wd[DI*DTR + d];
#pragma unroll
        for (int r = 0; r < DTR; r++) a += Xd[tl2*42 + r] * Wd[d*DTR + r];
        float sp = fmaxf(a, 0.f) + log1pf(__expf(-fabsf(a)));
        g_dt[(size_t)(t0 + tl2)*DI + d] = sp;
    }
}

// ======================================================================
// K3: scan pass A — local chunk scan, pipelined; stores h_end + dtsum.
// ======================================================================
__global__ __launch_bounds__(DI) void k_scanA(const float* __restrict__ A_log) {
    __shared__ float Bs[CSZ*DS];
    int d  = threadIdx.x;
    int b  = blockIdx.x >> 8;
    int ch = blockIdx.x & (NCH-1);
    int l0 = ch * CSZ;
    for (int li = d; li < CSZ*DS; li += DI)
        Bs[li] = g_Bm[(size_t)(b*LL + l0)*DS + li];
    __syncthreads();

    float Ad[DS], h[DS];
#pragma unroll
    for (int s = 0; s < DS; s++) { Ad[s] = -__expf(A_log[d*DS + s]); h[s] = 0.f; }
    float Ad0 = Ad[0];
    bool fast = true;
#pragma unroll
    for (int s = 1; s < DS; s++)
        fast = fast && (fabsf(Ad[s] - (s+1)*Ad0) <= 1e-4f * (float)(s+1) * fabsf(Ad0));

    float dtsum = 0.f;
    const float* dtp = g_dt + (size_t)(b*LL + l0)*DI + d;
    const float* xip = g_xi + (size_t)(b*LL + l0)*DI + d;

    float dtv = dtp[0];
    float xiv = xip[0];
    if (fast) {
#pragma unroll
        for (int t = 0; t < CSZ; t++) {
            float dtn = 0.f, xin = 0.f;
            if (t < CSZ-1) {
                dtn = dtp[(size_t)(t+1)*DI];
                xin = xip[(size_t)(t+1)*DI];
            }
            dtsum += dtv;
            float dx = dtv * xiv;
            float Ep[DS];
            build_pows(__expf(Ad0*dtv), Ep);
#pragma unroll
            for (int s = 0; s < DS; s++)
                h[s] = Ep[s] * h[s] + dx * Bs[t*DS + s];
            dtv = dtn; xiv = xin;
        }
    } else {
#pragma unroll
        for (int t = 0; t < CSZ; t++) {
            float dtn = 0.f, xin = 0.f;
            if (t < CSZ-1) {
                dtn = dtp[(size_t)(t+1)*DI];
                xin = xip[(size_t)(t+1)*DI];
            }
            dtsum += dtv;
            float dx = dtv * xiv;
#pragma unroll
            for (int s = 0; s < DS; s++)
                h[s] = __expf(Ad[s]*dtv) * h[s] + dx * Bs[t*DS + s];
            dtv = dtn; xiv = xin;
        }
    }
    size_t base = ((size_t)(b*NCH + ch)*DI + d)*DS;
    float4* pe = (float4*)(g_hend + base);
#pragma unroll
    for (int q = 0; q < 4; q++)
        pe[q] = make_float4(h[4*q], h[4*q+1], h[4*q+2], h[4*q+3]);
    g_dts[(size_t)(b*NCH + ch)*DI + d] = dtsum;
}

// ======================================================================
// K4a/b/c: parallel chunk combine.  P reconstructed as exp(Ad*dtsum).
// ======================================================================
__global__ __launch_bounds__(256) void k_scanB1(const float* __restrict__ A_log) {
    int r0 = blockIdx.x * 256 + threadIdx.x;   // row = d*DS + s
    int sc = blockIdx.y, b = blockIdx.z;
    float Ad = -__expf(A_log[r0]);
    int dd = r0 >> 4;
    size_t bh = ((size_t)(b*NCH) + sc*32)*ROWS + r0;
    size_t bd = ((size_t)(b*NCH) + sc*32)*DI + dd;
    float a = 1.f, bb = 0.f;
    float ds = g_dts[bd], hv = g_hend[bh];
#pragma unroll 4
    for (int c = 0; c < 32; c++) {
        float dsn = 0.f, hn = 0.f;
        if (c < 31) {
            dsn = g_dts[bd + (size_t)(c+1)*DI];
            hn  = g_hend[bh + (size_t)(c+1)*ROWS];
        }
        float P = __expf(Ad*ds);
        a = P*a;
        bb = P*bb + hv;
        ds = dsn; hv = hn;
    }
    size_t so = ((size_t)b*SUP + sc)*ROWS + r0;
    g_sP[so] = a;
    g_sH[so] = bb;
}

__global__ __launch_bounds__(256) void k_scanB2() {
    int idx = blockIdx.x * 256 + threadIdx.x;
    int b = idx / ROWS;
    int r = idx - b*ROWS;
    float H = 0.f;
#pragma unroll
    for (int sc = 0; sc < SUP; sc++) {
        size_t ofs = ((size_t)b*SUP + sc)*ROWS + r;
        g_sS[ofs] = H;
        H = g_sP[ofs]*H + g_sH[ofs];
    }
}

__global__ __launch_bounds__(256) void k_scanB3(const float* __restrict__ A_log) {
    int r0 = blockIdx.x * 256 + threadIdx.x;
    int sc = blockIdx.y, b = blockIdx.z;
    float Ad = -__expf(A_log[r0]);
    int dd = r0 >> 4;
    float H = g_sS[((size_t)b*SUP + sc)*ROWS + r0];
    size_t bh = ((size_t)(b*NCH) + sc*32)*ROWS + r0;
    size_t bd = ((size_t)(b*NCH) + sc*32)*DI + dd;
    float ds = g_dts[bd], hv = g_hend[bh];
#pragma unroll 4
    for (int c = 0; c < 32; c++) {
        float dsn = 0.f, hn = 0.f;
        if (c < 31) {
            dsn = g_dts[bd + (size_t)(c+1)*DI];
            hn  = g_hend[bh + (size_t)(c+1)*ROWS];
        }
        g_Hst[bh + (size_t)c*ROWS] = H;
        float P = __expf(Ad*ds);
        H = P*H + hv;
        ds = dsn; hv = hn;
    }
}

// ======================================================================
// K5: scan pass C — seeded re-scan + fused skip/gate, pipelined loads.
// ======================================================================
__global__ __launch_bounds__(DI) void k_scanC(const float* __restrict__ A_log,
                                              const float* __restrict__ Dp) {
    __shared__ float Bs[CSZ*DS];
    __shared__ float Cs[CSZ*DS];
    int d  = threadIdx.x;
    int b  = blockIdx.x >> 8;
    int ch = blockIdx.x & (NCH-1);
    int l0 = ch * CSZ;
    for (int li = d; li < CSZ*DS; li += DI) {
        Bs[li] = g_Bm[(size_t)(b*LL + l0)*DS + li];
        Cs[li] = g_Cm[(size_t)(b*LL + l0)*DS + li];
    }
    __syncthreads();

    float Ad[DS], h[DS];
#pragma unroll
    for (int s = 0; s < DS; s++) Ad[s] = -__expf(A_log[d*DS + s]);
    float Ad0 = Ad[0];
    bool fast = true;
#pragma unroll
    for (int s = 1; s < DS; s++)
        fast = fast && (fabsf(Ad[s] - (s+1)*Ad0) <= 1e-4f * (float)(s+1) * fabsf(Ad0));

    size_t hbase = ((size_t)(b*NCH + ch)*DI + d)*DS;
    const float4* hs = (const float4*)(g_Hst + hbase);
#pragma unroll
    for (int q = 0; q < 4; q++) {
        float4 v = hs[q];
        h[4*q] = v.x; h[4*q+1] = v.y; h[4*q+2] = v.z; h[4*q+3] = v.w;
    }
    float Dd = Dp[d];
    const float* dtp = g_dt + (size_t)(b*LL + l0)*DI + d;
    const float* xip = g_xi + (size_t)(b*LL + l0)*DI + d;
    const float* zp  = g_z  + (size_t)(b*LL + l0)*DI + d;
    float* outp      = g_ym + (size_t)(b*LL + l0)*DI + d;

    float dtv = dtp[0];
    float xiv = xip[0];
    float zv  = zp[0];
    if (fast) {
#pragma unroll
        for (int t = 0; t < CSZ; t++) {
            float dtn = 0.f, xin = 0.f, zn = 0.f;
            if (t < CSZ-1) {
                dtn = dtp[(size_t)(t+1)*DI];
                xin = xip[(size_t)(t+1)*DI];
                zn  = zp[(size_t)(t+1)*DI];
            }
            float dx = dtv * xiv;
            float Ep[DS];
            build_pows(__expf(Ad0*dtv), Ep);
            float y = 0.f;
#pragma unroll
            for (int s = 0; s < DS; s++) {
                h[s] = Ep[s]*h[s] + dx * Bs[t*DS + s];
                y += h[s] * Cs[t*DS + s];
            }
            float sz = zv / (1.f + __expf(-zv));
            outp[(size_t)t*DI] = (y + xiv*Dd) * sz;
            dtv = dtn; xiv = xin; zv = zn;
        }
    } else {
#pragma unroll
        for (int t = 0; t < CSZ; t++) {
            float dtn = 0.f, xin = 0.f, zn = 0.f;
            if (t < CSZ-1) {
                dtn = dtp[(size_t)(t+1)*DI];
                xin = xip[(size_t)(t+1)*DI];
                zn  = zp[(size_t)(t+1)*DI];
            }
            float dx = dtv * xiv;
            float y = 0.f;
#pragma unroll
            for (int s = 0; s < DS; s++) {
                h[s] = __expf(Ad[s]*dtv)*h[s] + dx * Bs[t*DS + s];
                y += h[s] * Cs[t*DS + s];
            }
            float sz = zv / (1.f + __expf(-zv));
            outp[(size_t)t*DI] = (y + xiv*Dd) * sz;
            dtv = dtn; xiv = xin; zv = zn;
        }
    }
}

// ======================================================================
// K6: out_proj GEMM (f32x2) -> [B, C, L]
// ======================================================================
__global__ __launch_bounds__(256) void k_outproj(const float* __restrict__ w) {
    __shared__ __align__(16) float As[64*66];
    __shared__ float Ws[64*49];
    int tid = threadIdx.x;
    int t0 = blockIdx.y * 64;
    int o0 = blockIdx.x * 48;
    int b  = t0 >> 12;
    int l0 = t0 & (LL-1);
    int tx = tid & 15, ty = tid >> 4;

    unsigned long long acc[2][3];
#pragma unroll
    for (int i = 0; i < 2; i++)
#pragma unroll
        for (int j = 0; j < 3; j++) acc[i][j] = 0ull;

    for (int ck = 0; ck < 3; ck++) {
        int c0 = ck * 64;
        for (int li = tid; li < 64*64; li += 256) {
            int tl = li >> 6, c = li & 63;
            As[c*66 + tl] = g_ym[(size_t)(t0 + tl)*DI + c0 + c];
        }
        for (int li = tid; li < 48*64; li += 256) {
            int ol = li >> 6, c = li & 63;
            Ws[c*49 + ol] = w[(o0 + ol)*DI + c0 + c];
        }
        __syncthreads();
#pragma unroll 8
        for (int c = 0; c < 64; c++) {
            unsigned long long a01 = *(const unsigned long long*)&As[c*66 + tx*4];
            unsigned long long a23 = *(const unsigned long long*)&As[c*66 + tx*4 + 2];
            float b0 = Ws[c*49 + ty*3 + 0];
            float b1 = Ws[c*49 + ty*3 + 1];
            float b2 = Ws[c*49 + ty*3 + 2];
            unsigned long long bd0 = pack2(b0, b0);
            unsigned long long bd1 = pack2(b1, b1);
            unsigned long long bd2 = pack2(b2, b2);
            ffma2(acc[0][0], a01, bd0); ffma2(acc[1][0], a23, bd0);
            ffma2(acc[0][1], a01, bd1); ffma2(acc[1][1], a23, bd1);
            ffma2(acc[0][2], a01, bd2); ffma2(acc[1][2], a23, bd2);
        }
        __syncthreads();
    }
#pragma unroll
    for (int j = 0; j < 3; j++) {
        int d = o0 + ty*3 + j;
        float2 lo = unpack2(acc[0][j]);
        float2 hi = unpack2(acc[1][j]);
        *(float4*)&g_xm[(size_t)(b*CCH + d)*LL + l0 + tx*4] = make_float4(lo.x, lo.y, hi.x, hi.y);
    }
}

// ======================================================================
// K7: 3x3 conv + BN + ReLU6 fused (R6/measured-best tiling).
// Tile: 8co x 8y x 64x; thread = 4co x 4px; ci chunks of 4; smem ~12.6KB.
// grid (12, 8, 4)
// ======================================================================
__global__ __launch_bounds__(256) void k_conv2d(const float* __restrict__ w,
                         const float* __restrict__ bng, const float* __restrict__ bnb,
                         const float* __restrict__ bnm, const float* __restrict__ bnv,
                         float* __restrict__ out) {
    __shared__ float in_s[4*10*66];             // 10.3 KB
    __shared__ __align__(8) float2 w2_s[4*9*8]; // 2.3 KB
    int tid = threadIdx.x;
    int co0 = blockIdx.x * 8;
    int y0  = blockIdx.y * 8;
    int b   = blockIdx.z;
    int cg = tid >> 7;            // 0..1 -> 4-co group
    int r  = tid & 127;
    int ty = r >> 4;              // 0..7
    int xg = r & 15;              // 0..15 -> x = xg*4

    unsigned long long acc[4][2];
#pragma unroll
    for (int co = 0; co < 4; co++) { acc[co][0] = 0ull; acc[co][1] = 0ull; }

    for (int cc = 0; cc < 24; cc++) {
        int ci0 = cc * 4;
        // main fill: 40 rows (4ci x 10rr), 4 quarters of 16 floats each
        if (tid < 160) {
            int rowid = tid >> 2, q = tid & 3;
            int ci = rowid / 10, rr = rowid - ci*10;
            int gy = y0 - 1 + rr;
            float4 v0, v1, v2, v3;
            if (gy >= 0 && gy < 64) {
                const float4* src = (const float4*)&g_xm[(((size_t)(b*CCH + ci0 + ci)*64 + gy)*64) + q*16];
                v0 = src[0]; v1 = src[1]; v2 = src[2]; v3 = src[3];
            } else {
                v0 = v1 = v2 = v3 = make_float4(0.f,0.f,0.f,0.f);
            }
            float* dstp = in_s + (ci*10 + rr)*66 + 1 + q*16;
            dstp[0]=v0.x;  dstp[1]=v0.y;  dstp[2]=v0.z;  dstp[3]=v0.w;
            dstp[4]=v1.x;  dstp[5]=v1.y;  dstp[6]=v1.z;  dstp[7]=v1.w;
            dstp[8]=v2.x;  dstp[9]=v2.y;  dstp[10]=v2.z; dstp[11]=v2.w;
            dstp[12]=v3.x; dstp[13]=v3.y; dstp[14]=v3.z; dstp[15]=v3.w;
        } else if (tid < 240) {
            // halo: 80 entries (40 rows x 2 sides)
            int li = tid - 160;
            int rowid = li >> 1, side = li & 1;
            int ci = rowid / 10, rr = rowid - ci*10;
            int gy = y0 - 1 + rr;
            int gx = side ? 64 : -1;
            float v = 0.f;
            if (gy >= 0 && gy < 64 && gx >= 0 && gx < 64)
                v = g_xm[((size_t)(b*CCH + ci0 + ci)*64 + gy)*64 + gx];
            in_s[(ci*10 + rr)*66 + (side ? 65 : 0)] = v;
        }
        for (int li = tid; li < 4*9*8; li += 256) {
            int ci = li / 72;
            int rem = li - ci*72;
            int k  = rem >> 3;
            int co = rem & 7;
            float wv = w[((co0 + co)*CCH + ci0 + ci)*9 + k];
            w2_s[(ci*9 + k)*8 + co] = make_float2(wv, wv);
        }
        __syncthreads();

        const unsigned long long* wsp = (const unsigned long long*)w2_s;
#pragma unroll
        for (int ci = 0; ci < 4; ci++) {
#pragma unroll
            for (int ky = 0; ky < 3; ky++) {
                const unsigned long long* row =
                    (const unsigned long long*)(in_s + ci*660 + (ty + ky)*66 + xg*4);
                unsigned long long u0 = row[0], u1 = row[1], u2 = row[2];
                float2 f0 = unpack2(u0), f1 = unpack2(u1);
                unsigned long long p12 = pack2(f0.y, f1.x);
                float2 f2 = unpack2(u2);
                unsigned long long p34 = pack2(f1.y, f2.x);
                const unsigned long long* wb = wsp + (size_t)(ci*9 + ky*3)*8 + cg*4;
#pragma unroll
                for (int co = 0; co < 4; co++) {
                    unsigned long long w0 = wb[co];
                    unsigned long long w1 = wb[8 + co];
                    unsigned long long w2v = wb[16 + co];
                    ffma2(acc[co][0], u0, w0);  ffma2(acc[co][1], u1, w0);
                    ffma2(acc[co][0], p12, w1); ffma2(acc[co][1], p34, w1);
                    ffma2(acc[co][0], u1, w2v); ffma2(acc[co][1], u2, w2v);
                }
            }
        }
        __syncthreads();
    }

#pragma unroll
    for (int co = 0; co < 4; co++) {
        int c = co0 + cg*4 + co;
        float inv = bng[c] * rsqrtf(bnv[c] + 1e-5f);
        float sh  = bnb[c] - bnm[c]*inv;
        float2 a0 = unpack2(acc[co][0]);
        float2 a1 = unpack2(acc[co][1]);
        float4 o;
        o.x = fminf(fmaxf(a0.x*inv + sh, 0.f), 6.f);
        o.y = fminf(fmaxf(a0.y*inv + sh, 0.f), 6.f);
        o.z = fminf(fmaxf(a1.x*inv + sh, 0.f), 6.f);
        o.w = fminf(fmaxf(a1.y*inv + sh, 0.f), 6.f);
        *(float4*)&out[((size_t)(b*CCH + c)*64 + y0 + ty)*64 + xg*4] = o;
    }
}

// ======================================================================
extern "C" void kernel_launch(void* const* d_in, const int* in_sizes, int n_in,
                              void* d_out, int out_size) {
    const float* x         = (const float*)d_in[0];
    const float* in_proj_w = (const float*)d_in[1];
    const float* conv1d_w  = (const float*)d_in[2];
    const float* conv1d_b  = (const float*)d_in[3];
    const float* x_proj_w  = (const float*)d_in[4];
    const float* dt_proj_w = (const float*)d_in[5];
    const float* dt_proj_b = (const float*)d_in[6];
    const float* A_log     = (const float*)d_in[7];
    const float* Dp        = (const float*)d_in[8];
    const float* out_proj_w= (const float*)d_in[9];
    const float* conv2d_w  = (const float*)d_in[10];
    const float* bn_g      = (const float*)d_in[11];
    const float* bn_b      = (const float*)d_in[12];
    const float* bn_m      = (const float*)d_in[13];
    const float* bn_v      = (const float*)d_in[14];
    float* out = (float*)d_out;

    k_inproj <<<dim3(6, 256), 256>>>(x, in_proj_w);
    k_conv1d <<<(NTOK/8)*48/256, 256>>>(conv1d_w, conv1d_b);
    k_xproj  <<<NTOK/64, 256>>>(x_proj_w, dt_proj_w, dt_proj_b);
    k_scanA  <<<BB*NCH, DI>>>(A_log);
    k_scanB1 <<<dim3(12, SUP, BB), 256>>>(A_log);
    k_scanB2 <<<BB*ROWS/256, 256>>>();
    k_scanB3 <<<dim3(12, SUP, BB), 256>>>(A_log);
    k_scanC  <<<BB*NCH, DI>>>(A_log, Dp);
    k_outproj<<<dim3(2, 256), 256>>>(out_proj_w);
    k_conv2d <<<dim3(12, 8, 4), 256>>>(conv2d_w, bn_g, bn_b, bn_m, bn_v, out);
}

// round 11
// speedup vs baseline: 1.2453x; 1.1819x over previous
#include <cuda_runtime.h>
#include <math.h>

#define BB   4
#define CCH  96
#define LL   4096
#define DI   192
#define DS   16
#define DTR  6
#define NTOK (BB*LL)      // 16384
#define NCH  256          // scan chunks per batch
#define CSZ  16           // chunk size
#define SUP  8            // super-chunks (32 chunks each)
#define ROWS (DI*DS)      // 3072
#define KTOT (CCH*9)      // 864

// ---------------- scratch ----------------
__device__ __align__(16) float g_xi_raw[NTOK*DI];
__device__ __align__(16) float g_z[NTOK*DI];
__device__ __align__(16) float g_xi[NTOK*DI];
__device__ __align__(16) float g_dt[NTOK*DI];
__device__ __align__(16) float g_Bm[NTOK*DS];
__device__ __align__(16) float g_Cm[NTOK*DS];
__device__ __align__(16) float g_dts[BB*NCH*DI];      // per-chunk dt sums
__device__ __align__(16) float g_hend[BB*NCH*ROWS];
__device__ __align__(16) float g_Hst[BB*NCH*ROWS];
__device__ __align__(16) float g_sP[BB*SUP*ROWS];
__device__ __align__(16) float g_sH[BB*SUP*ROWS];
__device__ __align__(16) float g_sS[BB*SUP*ROWS];
__device__ __align__(16) float g_ym[NTOK*DI];
__device__ __align__(16) float g_xm[BB*CCH*LL];
__device__ __align__(16) float g_wt[KTOT*CCH];        // transposed conv2d weights [k][co]

// ---------------- f32x2 helpers ----------------
__device__ __forceinline__ unsigned long long pack2(float lo, float hi) {
    unsigned long long r;
    asm("mov.b64 %0, {%1, %2};" : "=l"(r) : "f"(lo), "f"(hi));
    return r;
}
__device__ __forceinline__ void ffma2(unsigned long long &d, unsigned long long a, unsigned long long b) {
    asm("fma.rn.f32x2 %0, %1, %2, %3;" : "=l"(d) : "l"(a), "l"(b), "l"(d));
}
__device__ __forceinline__ float2 unpack2(unsigned long long v) {
    float2 f;
    asm("mov.b64 {%0, %1}, %2;" : "=f"(f.x), "=f"(f.y) : "l"(v));
    return f;
}
// Ep[s] = E^(s+1), log-depth tree
__device__ __forceinline__ void build_pows(float E, float* Ep) {
    Ep[0] = E;
#pragma unroll
    for (int s = 1; s < DS; s++) {
        int p = s + 1;
        Ep[s] = Ep[p/2 - 1] * Ep[p - p/2 - 1];
    }
}
__device__ __forceinline__ unsigned int to_tf32(float f) {
    unsigned int r;
    asm("cvt.rna.tf32.f32 %0, %1;" : "=r"(r) : "f"(f));
    return r;
}

// ======================================================================
// K1: in_proj GEMM (f32x2)
// ======================================================================
__global__ __launch_bounds__(256) void k_inproj(const float* __restrict__ x,
                                                const float* __restrict__ w) {
    __shared__ __align__(16) float As[48*64];
    __shared__ __align__(16) float Bs[48*66];
    int tid = threadIdx.x;
    int t0 = blockIdx.y * 64;
    int d0 = blockIdx.x * 64;
    int b  = t0 >> 12;
    int l0 = t0 & (LL-1);
    const float* xb = x + (size_t)b*CCH*LL + l0;

    int tx = tid & 15, ty = tid >> 4;
    unsigned long long acc[4][2];
#pragma unroll
    for (int i = 0; i < 4; i++) { acc[i][0] = 0ull; acc[i][1] = 0ull; }

    for (int ck = 0; ck < 2; ck++) {
        int cb = ck * 48;
        for (int li = tid; li < 48*64; li += 256) {
            int c = li >> 6, i = li & 63;
            As[c*64 + i] = xb[(size_t)(cb + c)*LL + i];
        }
        for (int li = tid; li < 64*48; li += 256) {
            int dl = li / 48, c = li - dl*48;
            Bs[c*66 + dl] = w[(d0 + dl)*CCH + cb + c];
        }
        __syncthreads();
#pragma unroll 8
        for (int c = 0; c < 48; c++) {
            float4 av = *(const float4*)&As[c*64 + ty*4];
            unsigned long long a0 = pack2(av.x, av.x);
            unsigned long long a1 = pack2(av.y, av.y);
            unsigned long long a2 = pack2(av.z, av.z);
            unsigned long long a3 = pack2(av.w, av.w);
            unsigned long long b01 = *(const unsigned long long*)&Bs[c*66 + tx*4];
            unsigned long long b23 = *(const unsigned long long*)&Bs[c*66 + tx*4 + 2];
            ffma2(acc[0][0], a0, b01); ffma2(acc[0][1], a0, b23);
            ffma2(acc[1][0], a1, b01); ffma2(acc[1][1], a1, b23);
            ffma2(acc[2][0], a2, b01); ffma2(acc[2][1], a2, b23);
            ffma2(acc[3][0], a3, b01); ffma2(acc[3][1], a3, b23);
        }
        __syncthreads();
    }
    float* dst; int dd;
    if (d0 < DI) { dst = g_xi_raw; dd = d0; } else { dst = g_z; dd = d0 - DI; }
#pragma unroll
    for (int i = 0; i < 4; i++) {
        int t = t0 + ty*4 + i;
        float2 lo = unpack2(acc[i][0]);
        float2 hi = unpack2(acc[i][1]);
        *(float4*)&dst[(size_t)t*DI + dd + tx*4] = make_float4(lo.x, lo.y, hi.x, hi.y);
    }
}

// ======================================================================
// K2a: depthwise causal conv1d + bias + SiLU (vectorized)
// ======================================================================
__global__ __launch_bounds__(256) void k_conv1d(const float* __restrict__ cw,
                                                const float* __restrict__ cb) {
    int gidx = blockIdx.x * 256 + threadIdx.x;
    int dvec = gidx % 48;
    int tg   = gidx / 48;
    int t0   = tg * 8;
    int l0   = t0 & (LL-1);
    int d4   = dvec * 4;

    float4 wk[4];
#pragma unroll
    for (int k = 0; k < 4; k++) {
        wk[k].x = cw[(d4+0)*4 + k];
        wk[k].y = cw[(d4+1)*4 + k];
        wk[k].z = cw[(d4+2)*4 + k];
        wk[k].w = cw[(d4+3)*4 + k];
    }
    float4 bias = *(const float4*)&cb[d4];

    float4 win[11];
#pragma unroll
    for (int j = 0; j < 11; j++) {
        int l = l0 - 3 + j;
        if (l >= 0)
            win[j] = *(const float4*)&g_xi_raw[(size_t)(t0 - 3 + j)*DI + d4];
        else
            win[j] = make_float4(0.f, 0.f, 0.f, 0.f);
    }

#pragma unroll
    for (int tt = 0; tt < 8; tt++) {
        float4 v = bias;
#pragma unroll
        for (int k = 0; k < 4; k++) {
            float4 u = win[tt + k];
            v.x += wk[k].x * u.x;
            v.y += wk[k].y * u.y;
            v.z += wk[k].z * u.z;
            v.w += wk[k].w * u.w;
        }
        v.x = v.x / (1.f + __expf(-v.x));
        v.y = v.y / (1.f + __expf(-v.y));
        v.z = v.z / (1.f + __expf(-v.z));
        v.w = v.w / (1.f + __expf(-v.w));
        *(float4*)&g_xi[(size_t)(t0 + tt)*DI + d4] = v;
    }
}

// ======================================================================
// K2b: x_dbl GEMM + dt proj (tiled)
// ======================================================================
__global__ __launch_bounds__(256) void k_xproj(const float* __restrict__ xpw,
                                               const float* __restrict__ dpw,
                                               const float* __restrict__ dpb) {
    __shared__ float As[64*49];
    __shared__ float Ws[48*48];
    __shared__ float Xd[64*42];
    __shared__ float Wd[DI*DTR + DI];
    int tid = threadIdx.x;
    int t0 = blockIdx.x * 64;
    int tx = tid & 15, ty = tid >> 4;

    for (int li = tid; li < DI*DTR; li += 256) Wd[li] = dpw[li];
    if (tid < DI) Wd[DI*DTR + tid] = dpb[tid];

    float acc[4][3];
#pragma unroll
    for (int i = 0; i < 4; i++)
#pragma unroll
        for (int j = 0; j < 3; j++) acc[i][j] = 0.f;

    for (int kc = 0; kc < 4; kc++) {
        int c0 = kc * 48;
        for (int li = tid; li < 64*48; li += 256) {
            int tk = li / 48, c = li - tk*48;
            As[tk*49 + c] = g_xi[(size_t)(t0 + tk)*DI + c0 + c];
        }
        for (int li = tid; li < 48*48; li += 256) {
            int j = li / 48, c = li - j*48;
            Ws[li] = (j < 38) ? xpw[j*DI + c0 + c] : 0.f;
        }
        __syncthreads();
#pragma unroll 8
        for (int c = 0; c < 48; c++) {
            float a0 = As[(tx*4 + 0)*49 + c];
            float a1 = As[(tx*4 + 1)*49 + c];
            float a2 = As[(tx*4 + 2)*49 + c];
            float a3 = As[(tx*4 + 3)*49 + c];
            float w0 = Ws[(ty*3 + 0)*48 + c];
            float w1 = Ws[(ty*3 + 1)*48 + c];
            float w2 = Ws[(ty*3 + 2)*48 + c];
            acc[0][0] += a0*w0; acc[0][1] += a0*w1; acc[0][2] += a0*w2;
            acc[1][0] += a1*w0; acc[1][1] += a1*w1; acc[1][2] += a1*w2;
            acc[2][0] += a2*w0; acc[2][1] += a2*w1; acc[2][2] += a2*w2;
            acc[3][0] += a3*w0; acc[3][1] += a3*w1; acc[3][2] += a3*w2;
        }
        __syncthreads();
    }

#pragma unroll
    for (int i = 0; i < 4; i++)
#pragma unroll
        for (int jj = 0; jj < 3; jj++) {
            int j = ty*3 + jj;
            if (j < 38) Xd[(tx*4 + i)*42 + j] = acc[i][jj];
        }
    __syncthreads();

    for (int li = tid; li < 64*DS; li += 256) {
        int t = li >> 4, s = li & 15;
        g_Bm[(size_t)(t0 + t)*DS + s] = Xd[t*42 + DTR + s];
        g_Cm[(size_t)(t0 + t)*DS + s] = Xd[t*42 + DTR + DS + s];
    }
    for (int idx = tid; idx < 64*DI; idx += 256) {
        int tl2 = idx / DI;
        int d = idx - tl2*DI;
        float a = Wd[DI*DTR + d];
#pragma unroll
        for (int r = 0; r < DTR; r++) a += Xd[tl2*42 + r] * Wd[d*DTR + r];
        float sp = fmaxf(a, 0.f) + log1pf(__expf(-fabsf(a)));
        g_dt[(size_t)(t0 + tl2)*DI + d] = sp;
    }
}

// ======================================================================
// K3: scan pass A — local chunk scan, pipelined; stores h_end + dtsum.
// ======================================================================
__global__ __launch_bounds__(DI) void k_scanA(const float* __restrict__ A_log) {
    __shared__ float Bs[CSZ*DS];
    int d  = threadIdx.x;
    int b  = blockIdx.x >> 8;
    int ch = blockIdx.x & (NCH-1);
    int l0 = ch * CSZ;
    for (int li = d; li < CSZ*DS; li += DI)
        Bs[li] = g_Bm[(size_t)(b*LL + l0)*DS + li];
    __syncthreads();

    float Ad[DS], h[DS];
#pragma unroll
    for (int s = 0; s < DS; s++) { Ad[s] = -__expf(A_log[d*DS + s]); h[s] = 0.f; }
    float Ad0 = Ad[0];
    bool fast = true;
#pragma unroll
    for (int s = 1; s < DS; s++)
        fast = fast && (fabsf(Ad[s] - (s+1)*Ad0) <= 1e-4f * (float)(s+1) * fabsf(Ad0));

    float dtsum = 0.f;
    const float* dtp = g_dt + (size_t)(b*LL + l0)*DI + d;
    const float* xip = g_xi + (size_t)(b*LL + l0)*DI + d;

    float dtv = dtp[0];
    float xiv = xip[0];
    if (fast) {
#pragma unroll
        for (int t = 0; t < CSZ; t++) {
            float dtn = 0.f, xin = 0.f;
            if (t < CSZ-1) {
                dtn = dtp[(size_t)(t+1)*DI];
                xin = xip[(size_t)(t+1)*DI];
            }
            dtsum += dtv;
            float dx = dtv * xiv;
            float Ep[DS];
            build_pows(__expf(Ad0*dtv), Ep);
#pragma unroll
            for (int s = 0; s < DS; s++)
                h[s] = Ep[s] * h[s] + dx * Bs[t*DS + s];
            dtv = dtn; xiv = xin;
        }
    } else {
#pragma unroll
        for (int t = 0; t < CSZ; t++) {
            float dtn = 0.f, xin = 0.f;
            if (t < CSZ-1) {
                dtn = dtp[(size_t)(t+1)*DI];
                xin = xip[(size_t)(t+1)*DI];
            }
            dtsum += dtv;
            float dx = dtv * xiv;
#pragma unroll
            for (int s = 0; s < DS; s++)
                h[s] = __expf(Ad[s]*dtv) * h[s] + dx * Bs[t*DS + s];
            dtv = dtn; xiv = xin;
        }
    }
    size_t base = ((size_t)(b*NCH + ch)*DI + d)*DS;
    float4* pe = (float4*)(g_hend + base);
#pragma unroll
    for (int q = 0; q < 4; q++)
        pe[q] = make_float4(h[4*q], h[4*q+1], h[4*q+2], h[4*q+3]);
    g_dts[(size_t)(b*NCH + ch)*DI + d] = dtsum;
}

// ======================================================================
// K4a/b/c: parallel chunk combine.  P reconstructed as exp(Ad*dtsum).
// ======================================================================
__global__ __launch_bounds__(256) void k_scanB1(const float* __restrict__ A_log) {
    int r0 = blockIdx.x * 256 + threadIdx.x;   // row = d*DS + s
    int sc = blockIdx.y, b = blockIdx.z;
    float Ad = -__expf(A_log[r0]);
    int dd = r0 >> 4;
    size_t bh = ((size_t)(b*NCH) + sc*32)*ROWS + r0;
    size_t bd = ((size_t)(b*NCH) + sc*32)*DI + dd;
    float a = 1.f, bb = 0.f;
    float ds = g_dts[bd], hv = g_hend[bh];
#pragma unroll 4
    for (int c = 0; c < 32; c++) {
        float dsn = 0.f, hn = 0.f;
        if (c < 31) {
            dsn = g_dts[bd + (size_t)(c+1)*DI];
            hn  = g_hend[bh + (size_t)(c+1)*ROWS];
        }
        float P = __expf(Ad*ds);
        a = P*a;
        bb = P*bb + hv;
        ds = dsn; hv = hn;
    }
    size_t so = ((size_t)b*SUP + sc)*ROWS + r0;
    g_sP[so] = a;
    g_sH[so] = bb;
}

__global__ __launch_bounds__(256) void k_scanB2() {
    int idx = blockIdx.x * 256 + threadIdx.x;
    int b = idx / ROWS;
    int r = idx - b*ROWS;
    float H = 0.f;
#pragma unroll
    for (int sc = 0; sc < SUP; sc++) {
        size_t ofs = ((size_t)b*SUP + sc)*ROWS + r;
        g_sS[ofs] = H;
        H = g_sP[ofs]*H + g_sH[ofs];
    }
}

__global__ __launch_bounds__(256) void k_scanB3(const float* __restrict__ A_log) {
    int r0 = blockIdx.x * 256 + threadIdx.x;
    int sc = blockIdx.y, b = blockIdx.z;
    float Ad = -__expf(A_log[r0]);
    int dd = r0 >> 4;
    float H = g_sS[((size_t)b*SUP + sc)*ROWS + r0];
    size_t bh = ((size_t)(b*NCH) + sc*32)*ROWS + r0;
    size_t bd = ((size_t)(b*NCH) + sc*32)*DI + dd;
    float ds = g_dts[bd], hv = g_hend[bh];
#pragma unroll 4
    for (int c = 0; c < 32; c++) {
        float dsn = 0.f, hn = 0.f;
        if (c < 31) {
            dsn = g_dts[bd + (size_t)(c+1)*DI];
            hn  = g_hend[bh + (size_t)(c+1)*ROWS];
        }
        g_Hst[bh + (size_t)c*ROWS] = H;
        float P = __expf(Ad*ds);
        H = P*H + hv;
        ds = dsn; hv = hn;
    }
}

// ======================================================================
// K5: scan pass C — seeded re-scan + fused skip/gate, pipelined loads.
// ======================================================================
__global__ __launch_bounds__(DI) void k_scanC(const float* __restrict__ A_log,
                                              const float* __restrict__ Dp) {
    __shared__ float Bs[CSZ*DS];
    __shared__ float Cs[CSZ*DS];
    int d  = threadIdx.x;
    int b  = blockIdx.x >> 8;
    int ch = blockIdx.x & (NCH-1);
    int l0 = ch * CSZ;
    for (int li = d; li < CSZ*DS; li += DI) {
        Bs[li] = g_Bm[(size_t)(b*LL + l0)*DS + li];
        Cs[li] = g_Cm[(size_t)(b*LL + l0)*DS + li];
    }
    __syncthreads();

    float Ad[DS], h[DS];
#pragma unroll
    for (int s = 0; s < DS; s++) Ad[s] = -__expf(A_log[d*DS + s]);
    float Ad0 = Ad[0];
    bool fast = true;
#pragma unroll
    for (int s = 1; s < DS; s++)
        fast = fast && (fabsf(Ad[s] - (s+1)*Ad0) <= 1e-4f * (float)(s+1) * fabsf(Ad0));

    size_t hbase = ((size_t)(b*NCH + ch)*DI + d)*DS;
    const float4* hs = (const float4*)(g_Hst + hbase);
#pragma unroll
    for (int q = 0; q < 4; q++) {
        float4 v = hs[q];
        h[4*q] = v.x; h[4*q+1] = v.y; h[4*q+2] = v.z; h[4*q+3] = v.w;
    }
    float Dd = Dp[d];
    const float* dtp = g_dt + (size_t)(b*LL + l0)*DI + d;
    const float* xip = g_xi + (size_t)(b*LL + l0)*DI + d;
    const float* zp  = g_z  + (size_t)(b*LL + l0)*DI + d;
    float* outp      = g_ym + (size_t)(b*LL + l0)*DI + d;

    float dtv = dtp[0];
    float xiv = xip[0];
    float zv  = zp[0];
    if (fast) {
#pragma unroll
        for (int t = 0; t < CSZ; t++) {
            float dtn = 0.f, xin = 0.f, zn = 0.f;
            if (t < CSZ-1) {
                dtn = dtp[(size_t)(t+1)*DI];
                xin = xip[(size_t)(t+1)*DI];
                zn  = zp[(size_t)(t+1)*DI];
            }
            float dx = dtv * xiv;
            float Ep[DS];
            build_pows(__expf(Ad0*dtv), Ep);
            float y = 0.f;
#pragma unroll
            for (int s = 0; s < DS; s++) {
                h[s] = Ep[s]*h[s] + dx * Bs[t*DS + s];
                y += h[s] * Cs[t*DS + s];
            }
            float sz = zv / (1.f + __expf(-zv));
            outp[(size_t)t*DI] = (y + xiv*Dd) * sz;
            dtv = dtn; xiv = xin; zv = zn;
        }
    } else {
#pragma unroll
        for (int t = 0; t < CSZ; t++) {
            float dtn = 0.f, xin = 0.f, zn = 0.f;
            if (t < CSZ-1) {
                dtn = dtp[(size_t)(t+1)*DI];
                xin = xip[(size_t)(t+1)*DI];
                zn  = zp[(size_t)(t+1)*DI];
            }
            float dx = dtv * xiv;
            float y = 0.f;
#pragma unroll
            for (int s = 0; s < DS; s++) {
                h[s] = __expf(Ad[s]*dtv)*h[s] + dx * Bs[t*DS + s];
                y += h[s] * Cs[t*DS + s];
            }
            float sz = zv / (1.f + __expf(-zv));
            outp[(size_t)t*DI] = (y + xiv*Dd) * sz;
            dtv = dtn; xiv = xin; zv = zn;
        }
    }
}

// ======================================================================
// K6: out_proj GEMM (f32x2) -> [B, C, L]
// ======================================================================
__global__ __launch_bounds__(256) void k_outproj(const float* __restrict__ w) {
    __shared__ __align__(16) float As[64*66];
    __shared__ float Ws[64*49];
    int tid = threadIdx.x;
    int t0 = blockIdx.y * 64;
    int o0 = blockIdx.x * 48;
    int b  = t0 >> 12;
    int l0 = t0 & (LL-1);
    int tx = tid & 15, ty = tid >> 4;

    unsigned long long acc[2][3];
#pragma unroll
    for (int i = 0; i < 2; i++)
#pragma unroll
        for (int j = 0; j < 3; j++) acc[i][j] = 0ull;

    for (int ck = 0; ck < 3; ck++) {
        int c0 = ck * 64;
        for (int li = tid; li < 64*64; li += 256) {
            int tl = li >> 6, c = li & 63;
            As[c*66 + tl] = g_ym[(size_t)(t0 + tl)*DI + c0 + c];
        }
        for (int li = tid; li < 48*64; li += 256) {
            int ol = li >> 6, c = li & 63;
            Ws[c*49 + ol] = w[(o0 + ol)*DI + c0 + c];
        }
        __syncthreads();
#pragma unroll 8
        for (int c = 0; c < 64; c++) {
            unsigned long long a01 = *(const unsigned long long*)&As[c*66 + tx*4];
            unsigned long long a23 = *(const unsigned long long*)&As[c*66 + tx*4 + 2];
            float b0 = Ws[c*49 + ty*3 + 0];
            float b1 = Ws[c*49 + ty*3 + 1];
            float b2 = Ws[c*49 + ty*3 + 2];
            unsigned long long bd0 = pack2(b0, b0);
            unsigned long long bd1 = pack2(b1, b1);
            unsigned long long bd2 = pack2(b2, b2);
            ffma2(acc[0][0], a01, bd0); ffma2(acc[1][0], a23, bd0);
            ffma2(acc[0][1], a01, bd1); ffma2(acc[1][1], a23, bd1);
            ffma2(acc[0][2], a01, bd2); ffma2(acc[1][2], a23, bd2);
        }
        __syncthreads();
    }
#pragma unroll
    for (int j = 0; j < 3; j++) {
        int d = o0 + ty*3 + j;
        float2 lo = unpack2(acc[0][j]);
        float2 hi = unpack2(acc[1][j]);
        *(float4*)&g_xm[(size_t)(b*CCH + d)*LL + l0 + tx*4] = make_float4(lo.x, lo.y, hi.x, hi.y);
    }
}

// ======================================================================
// K7a: transpose conv2d weights -> g_wt[k=864][co=96]
// ======================================================================
__global__ __launch_bounds__(256) void k_wprep(const float* __restrict__ w) {
    int idx = blockIdx.x * 256 + threadIdx.x;   // < 864*96
    if (idx < KTOT*CCH) {
        int k = idx / CCH, co = idx - k*CCH;
        g_wt[idx] = w[(size_t)co*KTOT + k];
    }
}

// ======================================================================
// K7b: 3x3 conv via tf32 mma.sync (implicit GEMM) + BN + ReLU6 fused.
// Block 128 thr (4 warps).  Tile: co 16 x (4 rows x 64 px) = 16 x 256.
// Warp w owns output row y0+w, 8 n-tiles of 8 px.  K = 96ci*9 in 12
// chunks of 8 ci (72 k = 9 mma k-steps each).
// grid (6 co-tiles, 16 y-tiles, 4 batch)
// ======================================================================
__global__ __launch_bounds__(128) void k_conv2d(
        const float* __restrict__ bng, const float* __restrict__ bnb,
        const float* __restrict__ bnm, const float* __restrict__ bnv,
        float* __restrict__ out) {
    __shared__ float Xs[8*6*66];     // 12.4 KB  [ci][row(y-1..y+4)][col(x+1)]
    __shared__ float Ws[72*16];      // 4.5 KB   [k_local][co]
    __shared__ int   offT[72];
    int tid = threadIdx.x;
    int lane = tid & 31, wid = tid >> 5;
    int co0 = blockIdx.x * 16;
    int y0  = blockIdx.y * 4;
    int b   = blockIdx.z;

    if (tid < 72) {
        int ci = tid / 9, r = tid - ci*9;
        offT[tid] = ci*396 + (r/3)*66 + (r - (r/3)*3);
    }
    // x-halo columns (0 and 65) are always outside the image -> zero once
    for (int li = tid; li < 96; li += 128) {
        int row = li >> 1, side = li & 1;
        Xs[row*66 + (side ? 65 : 0)] = 0.f;
    }

    float acc[8][4];
#pragma unroll
    for (int nt = 0; nt < 8; nt++)
#pragma unroll
        for (int q = 0; q < 4; q++) acc[nt][q] = 0.f;

    int arow = lane >> 2;      // co within tile (0..7)
    int kq   = lane & 3;       // k within 4

    for (int cc = 0; cc < 12; cc++) {
        int ci0 = cc * 8;
        __syncthreads();
        // interior fill: 48 rows x 16 float4
        for (int li = tid; li < 768; li += 128) {
            int row = li >> 4, q = li & 15;
            int ci = row / 6, yy = row - ci*6;
            int gy = y0 - 1 + yy;
            float4 v = make_float4(0.f, 0.f, 0.f, 0.f);
            if (gy >= 0 && gy < 64)
                v = *(const float4*)&g_xm[(((size_t)(b*CCH + ci0 + ci)*64 + gy)*64) + q*4];
            float* dp = Xs + row*66 + 1 + q*4;
            dp[0] = v.x; dp[1] = v.y; dp[2] = v.z; dp[3] = v.w;
        }
        // weights: Ws[k][co] from g_wt[(cc*72 + k)*96 + co0 + co]
        for (int li = tid; li < 72*16; li += 128) {
            int k = li >> 4, co = li & 15;
            Ws[li] = g_wt[(size_t)(cc*72 + k)*CCH + co0 + co];
        }
        __syncthreads();

#pragma unroll
        for (int kt = 0; kt < 9; kt++) {
            int k0 = kt*8 + kq;
            unsigned int a0 = to_tf32(Ws[(k0    )*16 + arow]);
            unsigned int a1 = to_tf32(Ws[(k0    )*16 + arow + 8]);
            unsigned int a2 = to_tf32(Ws[(k0 + 4)*16 + arow]);
            unsigned int a3 = to_tf32(Ws[(k0 + 4)*16 + arow + 8]);
            int off0 = offT[k0]     + wid*66;
            int off1 = offT[k0 + 4] + wid*66;
#pragma unroll
            for (int nt = 0; nt < 8; nt++) {
                int xq = nt*8 + (lane >> 2);
                unsigned int b0 = to_tf32(Xs[off0 + xq]);
                unsigned int b1 = to_tf32(Xs[off1 + xq]);
                asm volatile(
                    "mma.sync.aligned.m16n8k8.row.col.f32.tf32.tf32.f32 "
                    "{%0,%1,%2,%3}, {%4,%5,%6,%7}, {%8,%9}, {%0,%1,%2,%3};"
                    : "+f"(acc[nt][0]), "+f"(acc[nt][1]),
                      "+f"(acc[nt][2]), "+f"(acc[nt][3])
                    : "r"(a0), "r"(a1), "r"(a2), "r"(a3), "r"(b0), "r"(b1));
            }
        }
    }

    // epilogue: BN + ReLU6, store
    int c_lo = co0 + arow;
    int c_hi = c_lo + 8;
    float inv_lo = bng[c_lo] * rsqrtf(bnv[c_lo] + 1e-5f);
    float sh_lo  = bnb[c_lo] - bnm[c_lo]*inv_lo;
    float inv_hi = bng[c_hi] * rsqrtf(bnv[c_hi] + 1e-5f);
    float sh_hi  = bnb[c_hi] - bnm[c_hi]*inv_hi;
    int yrow = y0 + wid;
    int xb = (lane & 3)*2;
#pragma unroll
    for (int nt = 0; nt < 8; nt++) {
        int x = nt*8 + xb;
        float2 o0, o1;
        o0.x = fminf(fmaxf(acc[nt][0]*inv_lo + sh_lo, 0.f), 6.f);
        o0.y = fminf(fmaxf(acc[nt][1]*inv_lo + sh_lo, 0.f), 6.f);
        o1.x = fminf(fmaxf(acc[nt][2]*inv_hi + sh_hi, 0.f), 6.f);
        o1.y = fminf(fmaxf(acc[nt][3]*inv_hi + sh_hi, 0.f), 6.f);
        *(float2*)&out[((size_t)(b*CCH + c_lo)*64 + yrow)*64 + x] = o0;
        *(float2*)&out[((size_t)(b*CCH + c_hi)*64 + yrow)*64 + x] = o1;
    }
}

// ======================================================================
extern "C" void kernel_launch(void* const* d_in, const int* in_sizes, int n_in,
                              void* d_out, int out_size) {
    const float* x         = (const float*)d_in[0];
    const float* in_proj_w = (const float*)d_in[1];
    const float* conv1d_w  = (const float*)d_in[2];
    const float* conv1d_b  = (const float*)d_in[3];
    const float* x_proj_w  = (const float*)d_in[4];
    const float* dt_proj_w = (const float*)d_in[5];
    const float* dt_proj_b = (const float*)d_in[6];
    const float* A_log     = (const float*)d_in[7];
    const float* Dp        = (const float*)d_in[8];
    const float* out_proj_w= (const float*)d_in[9];
    const float* conv2d_w  = (const float*)d_in[10];
    const float* bn_g      = (const float*)d_in[11];
    const float* bn_b      = (const float*)d_in[12];
    const float* bn_m      = (const float*)d_in[13];
    const float* bn_v      = (const float*)d_in[14];
    float* out = (float*)d_out;

    k_wprep  <<<(KTOT*CCH + 255)/256, 256>>>(conv2d_w);
    k_inproj <<<dim3(6, 256), 256>>>(x, in_proj_w);
    k_conv1d <<<(NTOK/8)*48/256, 256>>>(conv1d_w, conv1d_b);
    k_xproj  <<<NTOK/64, 256>>>(x_proj_w, dt_proj_w, dt_proj_b);
    k_scanA  <<<BB*NCH, DI>>>(A_log);
    k_scanB1 <<<dim3(12, SUP, BB), 256>>>(A_log);
    k_scanB2 <<<BB*ROWS/256, 256>>>();
    k_scanB3 <<<dim3(12, SUP, BB), 256>>>(A_log);
    k_scanC  <<<BB*NCH, DI>>>(A_log, Dp);
    k_outproj<<<dim3(2, 256), 256>>>(out_proj_w);
    k_conv2d <<<dim3(6, 16, 4), 128>>>(bn_g, bn_b, bn_m, bn_v, out);
}

// round 12
// speedup vs baseline: 1.2870x; 1.0336x over previous
#include <cuda_runtime.h>
#include <math.h>

#define BB   4
#define CCH  96
#define LL   4096
#define DI   192
#define DS   16
#define DTR  6
#define NTOK (BB*LL)      // 16384
#define NCH  256          // scan chunks per batch
#define CSZ  16           // chunk size
#define SUP  8            // super-chunks (32 chunks each)
#define ROWS (DI*DS)      // 3072
#define KTOT (CCH*9)      // 864

// ---------------- scratch ----------------
__device__ __align__(16) float g_xi_raw[NTOK*DI];
__device__ __align__(16) float g_z[NTOK*DI];
__device__ __align__(16) float g_xi[NTOK*DI];
__device__ __align__(16) float g_dt[NTOK*DI];
__device__ __align__(16) float g_Bm[NTOK*DS];
__device__ __align__(16) float g_Cm[NTOK*DS];
__device__ __align__(16) float g_dts[BB*NCH*DI];      // per-chunk dt sums
__device__ __align__(16) float g_hend[BB*NCH*ROWS];
__device__ __align__(16) float g_Hst[BB*NCH*ROWS];
__device__ __align__(16) float g_sP[BB*SUP*ROWS];
__device__ __align__(16) float g_sH[BB*SUP*ROWS];
__device__ __align__(16) float g_sS[BB*SUP*ROWS];
__device__ __align__(16) float g_ym[NTOK*DI];
__device__ __align__(16) float g_xm[BB*CCH*LL];
__device__ __align__(16) float g_wt[KTOT*CCH];        // transposed conv2d weights [k][co]

// ---------------- f32x2 helpers ----------------
__device__ __forceinline__ unsigned long long pack2(float lo, float hi) {
    unsigned long long r;
    asm("mov.b64 %0, {%1, %2};" : "=l"(r) : "f"(lo), "f"(hi));
    return r;
}
__device__ __forceinline__ void ffma2(unsigned long long &d, unsigned long long a, unsigned long long b) {
    asm("fma.rn.f32x2 %0, %1, %2, %3;" : "=l"(d) : "l"(a), "l"(b), "l"(d));
}
__device__ __forceinline__ float2 unpack2(unsigned long long v) {
    float2 f;
    asm("mov.b64 {%0, %1}, %2;" : "=f"(f.x), "=f"(f.y) : "l"(v));
    return f;
}
// Ep[s] = E^(s+1), log-depth tree
__device__ __forceinline__ void build_pows(float E, float* Ep) {
    Ep[0] = E;
#pragma unroll
    for (int s = 1; s < DS; s++) {
        int p = s + 1;
        Ep[s] = Ep[p/2 - 1] * Ep[p - p/2 - 1];
    }
}
__device__ __forceinline__ unsigned int to_tf32(float f) {
    unsigned int r;
    asm("cvt.rna.tf32.f32 %0, %1;" : "=r"(r) : "f"(f));
    return r;
}

// ======================================================================
// K1: in_proj GEMM (f32x2)
// ======================================================================
__global__ __launch_bounds__(256) void k_inproj(const float* __restrict__ x,
                                                const float* __restrict__ w) {
    __shared__ __align__(16) float As[48*64];
    __shared__ __align__(16) float Bs[48*66];
    int tid = threadIdx.x;
    int t0 = blockIdx.y * 64;
    int d0 = blockIdx.x * 64;
    int b  = t0 >> 12;
    int l0 = t0 & (LL-1);
    const float* xb = x + (size_t)b*CCH*LL + l0;

    int tx = tid & 15, ty = tid >> 4;
    unsigned long long acc[4][2];
#pragma unroll
    for (int i = 0; i < 4; i++) { acc[i][0] = 0ull; acc[i][1] = 0ull; }

    for (int ck = 0; ck < 2; ck++) {
        int cb = ck * 48;
        for (int li = tid; li < 48*64; li += 256) {
            int c = li >> 6, i = li & 63;
            As[c*64 + i] = xb[(size_t)(cb + c)*LL + i];
        }
        for (int li = tid; li < 64*48; li += 256) {
            int dl = li / 48, c = li - dl*48;
            Bs[c*66 + dl] = w[(d0 + dl)*CCH + cb + c];
        }
        __syncthreads();
#pragma unroll 8
        for (int c = 0; c < 48; c++) {
            float4 av = *(const float4*)&As[c*64 + ty*4];
            unsigned long long a0 = pack2(av.x, av.x);
            unsigned long long a1 = pack2(av.y, av.y);
            unsigned long long a2 = pack2(av.z, av.z);
            unsigned long long a3 = pack2(av.w, av.w);
            unsigned long long b01 = *(const unsigned long long*)&Bs[c*66 + tx*4];
            unsigned long long b23 = *(const unsigned long long*)&Bs[c*66 + tx*4 + 2];
            ffma2(acc[0][0], a0, b01); ffma2(acc[0][1], a0, b23);
            ffma2(acc[1][0], a1, b01); ffma2(acc[1][1], a1, b23);
            ffma2(acc[2][0], a2, b01); ffma2(acc[2][1], a2, b23);
            ffma2(acc[3][0], a3, b01); ffma2(acc[3][1], a3, b23);
        }
        __syncthreads();
    }
    float* dst; int dd;
    if (d0 < DI) { dst = g_xi_raw; dd = d0; } else { dst = g_z; dd = d0 - DI; }
#pragma unroll
    for (int i = 0; i < 4; i++) {
        int t = t0 + ty*4 + i;
        float2 lo = unpack2(acc[i][0]);
        float2 hi = unpack2(acc[i][1]);
        *(float4*)&dst[(size_t)t*DI + dd + tx*4] = make_float4(lo.x, lo.y, hi.x, hi.y);
    }
}

// ======================================================================
// K2a: depthwise causal conv1d + bias + SiLU (vectorized)
// ======================================================================
__global__ __launch_bounds__(256) void k_conv1d(const float* __restrict__ cw,
                                                const float* __restrict__ cb) {
    int gidx = blockIdx.x * 256 + threadIdx.x;
    int dvec = gidx % 48;
    int tg   = gidx / 48;
    int t0   = tg * 8;
    int l0   = t0 & (LL-1);
    int d4   = dvec * 4;

    float4 wk[4];
#pragma unroll
    for (int k = 0; k < 4; k++) {
        wk[k].x = cw[(d4+0)*4 + k];
        wk[k].y = cw[(d4+1)*4 + k];
        wk[k].z = cw[(d4+2)*4 + k];
        wk[k].w = cw[(d4+3)*4 + k];
    }
    float4 bias = *(const float4*)&cb[d4];

    float4 win[11];
#pragma unroll
    for (int j = 0; j < 11; j++) {
        int l = l0 - 3 + j;
        if (l >= 0)
            win[j] = *(const float4*)&g_xi_raw[(size_t)(t0 - 3 + j)*DI + d4];
        else
            win[j] = make_float4(0.f, 0.f, 0.f, 0.f);
    }

#pragma unroll
    for (int tt = 0; tt < 8; tt++) {
        float4 v = bias;
#pragma unroll
        for (int k = 0; k < 4; k++) {
            float4 u = win[tt + k];
            v.x += wk[k].x * u.x;
            v.y += wk[k].y * u.y;
            v.z += wk[k].z * u.z;
            v.w += wk[k].w * u.w;
        }
        v.x = v.x / (1.f + __expf(-v.x));
        v.y = v.y / (1.f + __expf(-v.y));
        v.z = v.z / (1.f + __expf(-v.z));
        v.w = v.w / (1.f + __expf(-v.w));
        *(float4*)&g_xi[(size_t)(t0 + tt)*DI + d4] = v;
    }
}

// ======================================================================
// K2b: x_dbl GEMM + dt proj.  32 tokens/block -> 512 blocks (occupancy).
// Thread = 2 tok x 3 j (16 x 16).
// ======================================================================
__global__ __launch_bounds__(256) void k_xproj(const float* __restrict__ xpw,
                                               const float* __restrict__ dpw,
                                               const float* __restrict__ dpb) {
    __shared__ float As[32*49];
    __shared__ float Ws[48*48];
    __shared__ float Xd[32*42];
    __shared__ float Wd[DI*DTR + DI];
    int tid = threadIdx.x;
    int t0 = blockIdx.x * 32;
    int tg = tid & 15;         // token group (2 tok)
    int jg = tid >> 4;         // j group (3 j)

    for (int li = tid; li < DI*DTR; li += 256) Wd[li] = dpw[li];
    if (tid < DI) Wd[DI*DTR + tid] = dpb[tid];

    float acc[2][3];
#pragma unroll
    for (int i = 0; i < 2; i++)
#pragma unroll
        for (int j = 0; j < 3; j++) acc[i][j] = 0.f;

    for (int kc = 0; kc < 4; kc++) {
        int c0 = kc * 48;
        for (int li = tid; li < 32*48; li += 256) {
            int tk = li / 48, c = li - tk*48;
            As[tk*49 + c] = g_xi[(size_t)(t0 + tk)*DI + c0 + c];
        }
        for (int li = tid; li < 48*48; li += 256) {
            int j = li / 48, c = li - j*48;
            Ws[li] = (j < 38) ? xpw[j*DI + c0 + c] : 0.f;
        }
        __syncthreads();
#pragma unroll 8
        for (int c = 0; c < 48; c++) {
            float a0 = As[(tg*2 + 0)*49 + c];
            float a1 = As[(tg*2 + 1)*49 + c];
            float w0 = Ws[(jg*3 + 0)*48 + c];
            float w1 = Ws[(jg*3 + 1)*48 + c];
            float w2 = Ws[(jg*3 + 2)*48 + c];
            acc[0][0] += a0*w0; acc[0][1] += a0*w1; acc[0][2] += a0*w2;
            acc[1][0] += a1*w0; acc[1][1] += a1*w1; acc[1][2] += a1*w2;
        }
        __syncthreads();
    }

#pragma unroll
    for (int i = 0; i < 2; i++)
#pragma unroll
        for (int jj = 0; jj < 3; jj++) {
            int j = jg*3 + jj;
            if (j < 38) Xd[(tg*2 + i)*42 + j] = acc[i][jj];
        }
    __syncthreads();

    for (int li = tid; li < 32*DS; li += 256) {
        int t = li >> 4, s = li & 15;
        g_Bm[(size_t)(t0 + t)*DS + s] = Xd[t*42 + DTR + s];
        g_Cm[(size_t)(t0 + t)*DS + s] = Xd[t*42 + DTR + DS + s];
    }
    for (int idx = tid; idx < 32*DI; idx += 256) {
        int tl2 = idx / DI;
        int d = idx - tl2*DI;
        float a = Wd[DI*DTR + d];
#pragma unroll
        for (int r = 0; r < DTR; r++) a += Xd[tl2*42 + r] * Wd[d*DTR + r];
        float sp = fmaxf(a, 0.f) + log1pf(__expf(-fabsf(a)));
        g_dt[(size_t)(t0 + tl2)*DI + d] = sp;
    }
}

// ======================================================================
// K3: scan pass A — local chunk scan, pipelined; stores h_end + dtsum.
// ======================================================================
__global__ __launch_bounds__(DI) void k_scanA(const float* __restrict__ A_log) {
    __shared__ float Bs[CSZ*DS];
    int d  = threadIdx.x;
    int b  = blockIdx.x >> 8;
    int ch = blockIdx.x & (NCH-1);
    int l0 = ch * CSZ;
    for (int li = d; li < CSZ*DS; li += DI)
        Bs[li] = g_Bm[(size_t)(b*LL + l0)*DS + li];
    __syncthreads();

    float Ad[DS], h[DS];
#pragma unroll
    for (int s = 0; s < DS; s++) { Ad[s] = -__expf(A_log[d*DS + s]); h[s] = 0.f; }
    float Ad0 = Ad[0];
    bool fast = true;
#pragma unroll
    for (int s = 1; s < DS; s++)
        fast = fast && (fabsf(Ad[s] - (s+1)*Ad0) <= 1e-4f * (float)(s+1) * fabsf(Ad0));

    float dtsum = 0.f;
    const float* dtp = g_dt + (size_t)(b*LL + l0)*DI + d;
    const float* xip = g_xi + (size_t)(b*LL + l0)*DI + d;

    float dtv = dtp[0];
    float xiv = xip[0];
    if (fast) {
#pragma unroll
        for (int t = 0; t < CSZ; t++) {
            float dtn = 0.f, xin = 0.f;
            if (t < CSZ-1) {
                dtn = dtp[(size_t)(t+1)*DI];
                xin = xip[(size_t)(t+1)*DI];
            }
            dtsum += dtv;
            float dx = dtv * xiv;
            float Ep[DS];
            build_pows(__expf(Ad0*dtv), Ep);
#pragma unroll
            for (int s = 0; s < DS; s++)
                h[s] = Ep[s] * h[s] + dx * Bs[t*DS + s];
            dtv = dtn; xiv = xin;
        }
    } else {
#pragma unroll
        for (int t = 0; t < CSZ; t++) {
            float dtn = 0.f, xin = 0.f;
            if (t < CSZ-1) {
                dtn = dtp[(size_t)(t+1)*DI];
                xin = xip[(size_t)(t+1)*DI];
            }
            dtsum += dtv;
            float dx = dtv * xiv;
#pragma unroll
            for (int s = 0; s < DS; s++)
                h[s] = __expf(Ad[s]*dtv) * h[s] + dx * Bs[t*DS + s];
            dtv = dtn; xiv = xin;
        }
    }
    size_t base = ((size_t)(b*NCH + ch)*DI + d)*DS;
    float4* pe = (float4*)(g_hend + base);
#pragma unroll
    for (int q = 0; q < 4; q++)
        pe[q] = make_float4(h[4*q], h[4*q+1], h[4*q+2], h[4*q+3]);
    g_dts[(size_t)(b*NCH + ch)*DI + d] = dtsum;
}

// ======================================================================
// K4a/b/c: parallel chunk combine.  P reconstructed as exp(Ad*dtsum).
// ======================================================================
__global__ __launch_bounds__(256) void k_scanB1(const float* __restrict__ A_log) {
    int r0 = blockIdx.x * 256 + threadIdx.x;   // row = d*DS + s
    int sc = blockIdx.y, b = blockIdx.z;
    float Ad = -__expf(A_log[r0]);
    int dd = r0 >> 4;
    size_t bh = ((size_t)(b*NCH) + sc*32)*ROWS + r0;
    size_t bd = ((size_t)(b*NCH) + sc*32)*DI + dd;
    float a = 1.f, bb = 0.f;
    float ds = g_dts[bd], hv = g_hend[bh];
#pragma unroll 4
    for (int c = 0; c < 32; c++) {
        float dsn = 0.f, hn = 0.f;
        if (c < 31) {
            dsn = g_dts[bd + (size_t)(c+1)*DI];
            hn  = g_hend[bh + (size_t)(c+1)*ROWS];
        }
        float P = __expf(Ad*ds);
        a = P*a;
        bb = P*bb + hv;
        ds = dsn; hv = hn;
    }
    size_t so = ((size_t)b*SUP + sc)*ROWS + r0;
    g_sP[so] = a;
    g_sH[so] = bb;
}

__global__ __launch_bounds__(256) void k_scanB2() {
    int idx = blockIdx.x * 256 + threadIdx.x;
    int b = idx / ROWS;
    int r = idx - b*ROWS;
    float H = 0.f;
#pragma unroll
    for (int sc = 0; sc < SUP; sc++) {
        size_t ofs = ((size_t)b*SUP + sc)*ROWS + r;
        g_sS[ofs] = H;
        H = g_sP[ofs]*H + g_sH[ofs];
    }
}

__global__ __launch_bounds__(256) void k_scanB3(const float* __restrict__ A_log) {
    int r0 = blockIdx.x * 256 + threadIdx.x;
    int sc = blockIdx.y, b = blockIdx.z;
    float Ad = -__expf(A_log[r0]);
    int dd = r0 >> 4;
    float H = g_sS[((size_t)b*SUP + sc)*ROWS + r0];
    size_t bh = ((size_t)(b*NCH) + sc*32)*ROWS + r0;
    size_t bd = ((size_t)(b*NCH) + sc*32)*DI + dd;
    float ds = g_dts[bd], hv = g_hend[bh];
#pragma unroll 4
    for (int c = 0; c < 32; c++) {
        float dsn = 0.f, hn = 0.f;
        if (c < 31) {
            dsn = g_dts[bd + (size_t)(c+1)*DI];
            hn  = g_hend[bh + (size_t)(c+1)*ROWS];
        }
        g_Hst[bh + (size_t)c*ROWS] = H;
        float P = __expf(Ad*ds);
        H = P*H + hv;
        ds = dsn; hv = hn;
    }
}

// ======================================================================
// K5: scan pass C — seeded re-scan + fused skip/gate, pipelined loads.
// ======================================================================
__global__ __launch_bounds__(DI) void k_scanC(const float* __restrict__ A_log,
                                              const float* __restrict__ Dp) {
    __shared__ float Bs[CSZ*DS];
    __shared__ float Cs[CSZ*DS];
    int d  = threadIdx.x;
    int b  = blockIdx.x >> 8;
    int ch = blockIdx.x & (NCH-1);
    int l0 = ch * CSZ;
    for (int li = d; li < CSZ*DS; li += DI) {
        Bs[li] = g_Bm[(size_t)(b*LL + l0)*DS + li];
        Cs[li] = g_Cm[(size_t)(b*LL + l0)*DS + li];
    }
    __syncthreads();

    float Ad[DS], h[DS];
#pragma unroll
    for (int s = 0; s < DS; s++) Ad[s] = -__expf(A_log[d*DS + s]);
    float Ad0 = Ad[0];
    bool fast = true;
#pragma unroll
    for (int s = 1; s < DS; s++)
        fast = fast && (fabsf(Ad[s] - (s+1)*Ad0) <= 1e-4f * (float)(s+1) * fabsf(Ad0));

    size_t hbase = ((size_t)(b*NCH + ch)*DI + d)*DS;
    const float4* hs = (const float4*)(g_Hst + hbase);
#pragma unroll
    for (int q = 0; q < 4; q++) {
        float4 v = hs[q];
        h[4*q] = v.x; h[4*q+1] = v.y; h[4*q+2] = v.z; h[4*q+3] = v.w;
    }
    float Dd = Dp[d];
    const float* dtp = g_dt + (size_t)(b*LL + l0)*DI + d;
    const float* xip = g_xi + (size_t)(b*LL + l0)*DI + d;
    const float* zp  = g_z  + (size_t)(b*LL + l0)*DI + d;
    float* outp      = g_ym + (size_t)(b*LL + l0)*DI + d;

    float dtv = dtp[0];
    float xiv = xip[0];
    float zv  = zp[0];
    if (fast) {
#pragma unroll
        for (int t = 0; t < CSZ; t++) {
            float dtn = 0.f, xin = 0.f, zn = 0.f;
            if (t < CSZ-1) {
                dtn = dtp[(size_t)(t+1)*DI];
                xin = xip[(size_t)(t+1)*DI];
                zn  = zp[(size_t)(t+1)*DI];
            }
            float dx = dtv * xiv;
            float Ep[DS];
            build_pows(__expf(Ad0*dtv), Ep);
            float y = 0.f;
#pragma unroll
            for (int s = 0; s < DS; s++) {
                h[s] = Ep[s]*h[s] + dx * Bs[t*DS + s];
                y += h[s] * Cs[t*DS + s];
            }
            float sz = zv / (1.f + __expf(-zv));
            outp[(size_t)t*DI] = (y + xiv*Dd) * sz;
            dtv = dtn; xiv = xin; zv = zn;
        }
    } else {
#pragma unroll
        for (int t = 0; t < CSZ; t++) {
            float dtn = 0.f, xin = 0.f, zn = 0.f;
            if (t < CSZ-1) {
                dtn = dtp[(size_t)(t+1)*DI];
                xin = xip[(size_t)(t+1)*DI];
                zn  = zp[(size_t)(t+1)*DI];
            }
            float dx = dtv * xiv;
            float y = 0.f;
#pragma unroll
            for (int s = 0; s < DS; s++) {
                h[s] = __expf(Ad[s]*dtv)*h[s] + dx * Bs[t*DS + s];
                y += h[s] * Cs[t*DS + s];
            }
            float sz = zv / (1.f + __expf(-zv));
            outp[(size_t)t*DI] = (y + xiv*Dd) * sz;
            dtv = dtn; xiv = xin; zv = zn;
        }
    }
}

// ======================================================================
// K6: out_proj GEMM (f32x2) -> [B, C, L]
// ======================================================================
__global__ __launch_bounds__(256) void k_outproj(const float* __restrict__ w) {
    __shared__ __align__(16) float As[64*66];
    __shared__ float Ws[64*49];
    int tid = threadIdx.x;
    int t0 = blockIdx.y * 64;
    int o0 = blockIdx.x * 48;
    int b  = t0 >> 12;
    int l0 = t0 & (LL-1);
    int tx = tid & 15, ty = tid >> 4;

    unsigned long long acc[2][3];
#pragma unroll
    for (int i = 0; i < 2; i++)
#pragma unroll
        for (int j = 0; j < 3; j++) acc[i][j] = 0ull;

    for (int ck = 0; ck < 3; ck++) {
        int c0 = ck * 64;
        for (int li = tid; li < 64*64; li += 256) {
            int tl = li >> 6, c = li & 63;
            As[c*66 + tl] = g_ym[(size_t)(t0 + tl)*DI + c0 + c];
        }
        for (int li = tid; li < 48*64; li += 256) {
            int ol = li >> 6, c = li & 63;
            Ws[c*49 + ol] = w[(o0 + ol)*DI + c0 + c];
        }
        __syncthreads();
#pragma unroll 8
        for (int c = 0; c < 64; c++) {
            unsigned long long a01 = *(const unsigned long long*)&As[c*66 + tx*4];
            unsigned long long a23 = *(const unsigned long long*)&As[c*66 + tx*4 + 2];
            float b0 = Ws[c*49 + ty*3 + 0];
            float b1 = Ws[c*49 + ty*3 + 1];
            float b2 = Ws[c*49 + ty*3 + 2];
            unsigned long long bd0 = pack2(b0, b0);
            unsigned long long bd1 = pack2(b1, b1);
            unsigned long long bd2 = pack2(b2, b2);
            ffma2(acc[0][0], a01, bd0); ffma2(acc[1][0], a23, bd0);
            ffma2(acc[0][1], a01, bd1); ffma2(acc[1][1], a23, bd1);
            ffma2(acc[0][2], a01, bd2); ffma2(acc[1][2], a23, bd2);
        }
        __syncthreads();
    }
#pragma unroll
    for (int j = 0; j < 3; j++) {
        int d = o0 + ty*3 + j;
        float2 lo = unpack2(acc[0][j]);
        float2 hi = unpack2(acc[1][j]);
        *(float4*)&g_xm[(size_t)(b*CCH + d)*LL + l0 + tx*4] = make_float4(lo.x, lo.y, hi.x, hi.y);
    }
}

// ======================================================================
// K7a: transpose conv2d weights -> g_wt[k=864][co=96]
// ======================================================================
__global__ __launch_bounds__(256) void k_wprep(const float* __restrict__ w) {
    int idx = blockIdx.x * 256 + threadIdx.x;   // < 864*96
    if (idx < KTOT*CCH) {
        int k = idx / CCH, co = idx - k*CCH;
        g_wt[idx] = w[(size_t)co*KTOT + k];
    }
}

// ======================================================================
// K7b: 3x3 conv via tf32 mma.sync (implicit GEMM) + BN + ReLU6 fused.
// Block 128 thr (4 warps).  Tile: co 16 x (4 rows x 64 px) = 16 x 256.
// grid (6 co-tiles, 16 y-tiles, 4 batch)
// ======================================================================
__global__ __launch_bounds__(128) void k_conv2d(
        const float* __restrict__ bng, const float* __restrict__ bnb,
        const float* __restrict__ bnm, const float* __restrict__ bnv,
        float* __restrict__ out) {
    __shared__ float Xs[8*6*66];     // 12.4 KB  [ci][row(y-1..y+4)][col(x+1)]
    __shared__ float Ws[72*16];      // 4.5 KB   [k_local][co]
    __shared__ int   offT[72];
    int tid = threadIdx.x;
    int lane = tid & 31, wid = tid >> 5;
    int co0 = blockIdx.x * 16;
    int y0  = blockIdx.y * 4;
    int b   = blockIdx.z;

    if (tid < 72) {
        int ci = tid / 9, r = tid - ci*9;
        offT[tid] = ci*396 + (r/3)*66 + (r - (r/3)*3);
    }
    // x-halo columns (0 and 65) are always outside the image -> zero once
    for (int li = tid; li < 96; li += 128) {
        int row = li >> 1, side = li & 1;
        Xs[row*66 + (side ? 65 : 0)] = 0.f;
    }

    float acc[8][4];
#pragma unroll
    for (int nt = 0; nt < 8; nt++)
#pragma unroll
        for (int q = 0; q < 4; q++) acc[nt][q] = 0.f;

    int arow = lane >> 2;      // co within tile (0..7)
    int kq   = lane & 3;       // k within 4

    for (int cc = 0; cc < 12; cc++) {
        int ci0 = cc * 8;
        __syncthreads();
        // interior fill: 48 rows x 16 float4
        for (int li = tid; li < 768; li += 128) {
            int row = li >> 4, q = li & 15;
            int ci = row / 6, yy = row - ci*6;
            int gy = y0 - 1 + yy;
            float4 v = make_float4(0.f, 0.f, 0.f, 0.f);
            if (gy >= 0 && gy < 64)
                v = *(const float4*)&g_xm[(((size_t)(b*CCH + ci0 + ci)*64 + gy)*64) + q*4];
            float* dp = Xs + row*66 + 1 + q*4;
            dp[0] = v.x; dp[1] = v.y; dp[2] = v.z; dp[3] = v.w;
        }
        // weights: Ws[k][co] from g_wt[(cc*72 + k)*96 + co0 + co]
        for (int li = tid; li < 72*16; li += 128) {
            int k = li >> 4, co = li & 15;
            Ws[li] = g_wt[(size_t)(cc*72 + k)*CCH + co0 + co];
        }
        __syncthreads();

#pragma unroll
        for (int kt = 0; kt < 9; kt++) {
            int k0 = kt*8 + kq;
            unsigned int a0 = to_tf32(Ws[(k0    )*16 + arow]);
            unsigned int a1 = to_tf32(Ws[(k0    )*16 + arow + 8]);
            unsigned int a2 = to_tf32(Ws[(k0 + 4)*16 + arow]);
            unsigned int a3 = to_tf32(Ws[(k0 + 4)*16 + arow + 8]);
            int off0 = offT[k0]     + wid*66;
            int off1 = offT[k0 + 4] + wid*66;
#pragma unroll
            for (int nt = 0; nt < 8; nt++) {
                int xq = nt*8 + (lane >> 2);
                unsigned int b0 = to_tf32(Xs[off0 + xq]);
                unsigned int b1 = to_tf32(Xs[off1 + xq]);
                asm volatile(
                    "mma.sync.aligned.m16n8k8.row.col.f32.tf32.tf32.f32 "
                    "{%0,%1,%2,%3}, {%4,%5,%6,%7}, {%8,%9}, {%0,%1,%2,%3};"
                    : "+f"(acc[nt][0]), "+f"(acc[nt][1]),
                      "+f"(acc[nt][2]), "+f"(acc[nt][3])
                    : "r"(a0), "r"(a1), "r"(a2), "r"(a3), "r"(b0), "r"(b1));
            }
        }
    }

    // epilogue: BN + ReLU6, store
    int c_lo = co0 + arow;
    int c_hi = c_lo + 8;
    float inv_lo = bng[c_lo] * rsqrtf(bnv[c_lo] + 1e-5f);
    float sh_lo  = bnb[c_lo] - bnm[c_lo]*inv_lo;
    float inv_hi = bng[c_hi] * rsqrtf(bnv[c_hi] + 1e-5f);
    float sh_hi  = bnb[c_hi] - bnm[c_hi]*inv_hi;
    int yrow = y0 + wid;
    int xb = (lane & 3)*2;
#pragma unroll
    for (int nt = 0; nt < 8; nt++) {
        int x = nt*8 + xb;
        float2 o0, o1;
        o0.x = fminf(fmaxf(acc[nt][0]*inv_lo + sh_lo, 0.f), 6.f);
        o0.y = fminf(fmaxf(acc[nt][1]*inv_lo + sh_lo, 0.f), 6.f);
        o1.x = fminf(fmaxf(acc[nt][2]*inv_hi + sh_hi, 0.f), 6.f);
        o1.y = fminf(fmaxf(acc[nt][3]*inv_hi + sh_hi, 0.f), 6.f);
        *(float2*)&out[((size_t)(b*CCH + c_lo)*64 + yrow)*64 + x] = o0;
        *(float2*)&out[((size_t)(b*CCH + c_hi)*64 + yrow)*64 + x] = o1;
    }
}

// ======================================================================
extern "C" void kernel_launch(void* const* d_in, const int* in_sizes, int n_in,
                              void* d_out, int out_size) {
    const float* x         = (const float*)d_in[0];
    const float* in_proj_w = (const float*)d_in[1];
    const float* conv1d_w  = (const float*)d_in[2];
    const float* conv1d_b  = (const float*)d_in[3];
    const float* x_proj_w  = (const float*)d_in[4];
    const float* dt_proj_w = (const float*)d_in[5];
    const float* dt_proj_b = (const float*)d_in[6];
    const float* A_log     = (const float*)d_in[7];
    const float* Dp        = (const float*)d_in[8];
    const float* out_proj_w= (const float*)d_in[9];
    const float* conv2d_w  = (const float*)d_in[10];
    const float* bn_g      = (const float*)d_in[11];
    const float* bn_b      = (const float*)d_in[12];
    const float* bn_m      = (const float*)d_in[13];
    const float* bn_v      = (const float*)d_in[14];
    float* out = (float*)d_out;

    k_wprep  <<<(KTOT*CCH + 255)/256, 256>>>(conv2d_w);
    k_inproj <<<dim3(6, 256), 256>>>(x, in_proj_w);
    k_conv1d <<<(NTOK/8)*48/256, 256>>>(conv1d_w, conv1d_b);
    k_xproj  <<<NTOK/32, 256>>>(x_proj_w, dt_proj_w, dt_proj_b);
    k_scanA  <<<BB*NCH, DI>>>(A_log);
    k_scanB1 <<<dim3(12, SUP, BB), 256>>>(A_log);
    k_scanB2 <<<BB*ROWS/256, 256>>>();
    k_scanB3 <<<dim3(12, SUP, BB), 256>>>(A_log);
    k_scanC  <<<BB*NCH, DI>>>(A_log, Dp);
    k_outproj<<<dim3(2, 256), 256>>>(out_proj_w);
    k_conv2d <<<dim3(6, 16, 4), 128>>>(bn_g, bn_b, bn_m, bn_v, out);
}

// round 14
// speedup vs baseline: 1.3078x; 1.0161x over previous
#include <cuda_runtime.h>
#include <math.h>

#define BB   4
#define CCH  96
#define LL   4096
#define DI   192
#define DS   16
#define DTR  6
#define NTOK (BB*LL)      // 16384
#define NCH  256          // scan chunks per batch
#define CSZ  16           // chunk size
#define SUP  8            // super-chunks (32 chunks each)
#define ROWS (DI*DS)      // 3072
#define KTOT (CCH*9)      // 864

// ---------------- scratch ----------------
__device__ __align__(16) float g_xi_raw[NTOK*DI];
__device__ __align__(16) float g_z[NTOK*DI];
__device__ __align__(16) float g_xi[NTOK*DI];
__device__ __align__(16) float g_dt[NTOK*DI];
__device__ __align__(16) float g_Bm[NTOK*DS];
__device__ __align__(16) float g_Cm[NTOK*DS];
__device__ __align__(16) float g_dts[BB*NCH*DI];      // per-chunk dt sums
__device__ __align__(16) float g_hend[BB*NCH*ROWS];
__device__ __align__(16) float g_Hst[BB*NCH*ROWS];
__device__ __align__(16) float g_sP[BB*SUP*ROWS];
__device__ __align__(16) float g_sH[BB*SUP*ROWS];
__device__ __align__(16) float g_sS[BB*SUP*ROWS];
__device__ __align__(16) float g_ym[NTOK*DI];
__device__ __align__(16) float g_xm[BB*CCH*LL];
__device__ __align__(16) float g_wt[KTOT*CCH];        // transposed conv2d weights [k][co]

// ---------------- f32x2 helpers ----------------
__device__ __forceinline__ unsigned long long pack2(float lo, float hi) {
    unsigned long long r;
    asm("mov.b64 %0, {%1, %2};" : "=l"(r) : "f"(lo), "f"(hi));
    return r;
}
__device__ __forceinline__ void ffma2(unsigned long long &d, unsigned long long a, unsigned long long b) {
    asm("fma.rn.f32x2 %0, %1, %2, %3;" : "=l"(d) : "l"(a), "l"(b), "l"(d));
}
__device__ __forceinline__ float2 unpack2(unsigned long long v) {
    float2 f;
    asm("mov.b64 {%0, %1}, %2;" : "=f"(f.x), "=f"(f.y) : "l"(v));
    return f;
}
// Ep[s] = E^(s+1), log-depth tree
__device__ __forceinline__ void build_pows(float E, float* Ep) {
    Ep[0] = E;
#pragma unroll
    for (int s = 1; s < DS; s++) {
        int p = s + 1;
        Ep[s] = Ep[p/2 - 1] * Ep[p - p/2 - 1];
    }
}
__device__ __forceinline__ unsigned int to_tf32(float f) {
    unsigned int r;
    asm("cvt.rna.tf32.f32 %0, %1;" : "=r"(r) : "f"(f));
    return r;
}

// ======================================================================
// K1: in_proj GEMM (f32x2)
// ======================================================================
__global__ __launch_bounds__(256) void k_inproj(const float* __restrict__ x,
                                                const float* __restrict__ w) {
    __shared__ __align__(16) float As[48*64];
    __shared__ __align__(16) float Bs[48*66];
    int tid = threadIdx.x;
    int t0 = blockIdx.y * 64;
    int d0 = blockIdx.x * 64;
    int b  = t0 >> 12;
    int l0 = t0 & (LL-1);
    const float* xb = x + (size_t)b*CCH*LL + l0;

    int tx = tid & 15, ty = tid >> 4;
    unsigned long long acc[4][2];
#pragma unroll
    for (int i = 0; i < 4; i++) { acc[i][0] = 0ull; acc[i][1] = 0ull; }

    for (int ck = 0; ck < 2; ck++) {
        int cb = ck * 48;
        for (int li = tid; li < 48*64; li += 256) {
            int c = li >> 6, i = li & 63;
            As[c*64 + i] = xb[(size_t)(cb + c)*LL + i];
        }
        for (int li = tid; li < 64*48; li += 256) {
            int dl = li / 48, c = li - dl*48;
            Bs[c*66 + dl] = w[(d0 + dl)*CCH + cb + c];
        }
        __syncthreads();
#pragma unroll 8
        for (int c = 0; c < 48; c++) {
            float4 av = *(const float4*)&As[c*64 + ty*4];
            unsigned long long a0 = pack2(av.x, av.x);
            unsigned long long a1 = pack2(av.y, av.y);
            unsigned long long a2 = pack2(av.z, av.z);
            unsigned long long a3 = pack2(av.w, av.w);
            unsigned long long b01 = *(const unsigned long long*)&Bs[c*66 + tx*4];
            unsigned long long b23 = *(const unsigned long long*)&Bs[c*66 + tx*4 + 2];
            ffma2(acc[0][0], a0, b01); ffma2(acc[0][1], a0, b23);
            ffma2(acc[1][0], a1, b01); ffma2(acc[1][1], a1, b23);
            ffma2(acc[2][0], a2, b01); ffma2(acc[2][1], a2, b23);
            ffma2(acc[3][0], a3, b01); ffma2(acc[3][1], a3, b23);
        }
        __syncthreads();
    }
    float* dst; int dd;
    if (d0 < DI) { dst = g_xi_raw; dd = d0; } else { dst = g_z; dd = d0 - DI; }
#pragma unroll
    for (int i = 0; i < 4; i++) {
        int t = t0 + ty*4 + i;
        float2 lo = unpack2(acc[i][0]);
        float2 hi = unpack2(acc[i][1]);
        *(float4*)&dst[(size_t)t*DI + dd + tx*4] = make_float4(lo.x, lo.y, hi.x, hi.y);
    }
}

// ======================================================================
// K2a: depthwise causal conv1d + bias + SiLU (vectorized)
// ======================================================================
__global__ __launch_bounds__(256) void k_conv1d(const float* __restrict__ cw,
                                                const float* __restrict__ cb) {
    int gidx = blockIdx.x * 256 + threadIdx.x;
    int dvec = gidx % 48;
    int tg   = gidx / 48;
    int t0   = tg * 8;
    int l0   = t0 & (LL-1);
    int d4   = dvec * 4;

    float4 wk[4];
#pragma unroll
    for (int k = 0; k < 4; k++) {
        wk[k].x = cw[(d4+0)*4 + k];
        wk[k].y = cw[(d4+1)*4 + k];
        wk[k].z = cw[(d4+2)*4 + k];
        wk[k].w = cw[(d4+3)*4 + k];
    }
    float4 bias = *(const float4*)&cb[d4];

    float4 win[11];
#pragma unroll
    for (int j = 0; j < 11; j++) {
        int l = l0 - 3 + j;
        if (l >= 0)
            win[j] = *(const float4*)&g_xi_raw[(size_t)(t0 - 3 + j)*DI + d4];
        else
            win[j] = make_float4(0.f, 0.f, 0.f, 0.f);
    }

#pragma unroll
    for (int tt = 0; tt < 8; tt++) {
        float4 v = bias;
#pragma unroll
        for (int k = 0; k < 4; k++) {
            float4 u = win[tt + k];
            v.x += wk[k].x * u.x;
            v.y += wk[k].y * u.y;
            v.z += wk[k].z * u.z;
            v.w += wk[k].w * u.w;
        }
        v.x = v.x / (1.f + __expf(-v.x));
        v.y = v.y / (1.f + __expf(-v.y));
        v.z = v.z / (1.f + __expf(-v.z));
        v.w = v.w / (1.f + __expf(-v.w));
        *(float4*)&g_xi[(size_t)(t0 + tt)*DI + d4] = v;
    }
}

// ======================================================================
// K2b: x_dbl GEMM + dt proj.  64 tok/block, 192 threads.
// Thread = 4 tok x 4 j (j padded to 48).  float2 operand reads.
// Xd aliases As; Wd aliases Ws (post-mainloop).
// ======================================================================
__global__ __launch_bounds__(192) void k_xproj(const float* __restrict__ xpw,
                                               const float* __restrict__ dpw,
                                               const float* __restrict__ dpb) {
    __shared__ __align__(16) float As[48*66];   // [c][tok]; later Xd[64*42]
    __shared__ __align__(16) float Ws[48*50];   // [c][j];   later Wd[DI*DTR+DI]
    int tid = threadIdx.x;
    int t0 = blockIdx.x * 64;
    int tg = tid & 15;          // 4 tokens: tg*4..tg*4+3
    int jg = tid >> 4;          // 0..11 -> 4 j's: jg*4..jg*4+3

    float acc[4][4];
#pragma unroll
    for (int i = 0; i < 4; i++)
#pragma unroll
        for (int j = 0; j < 4; j++) acc[i][j] = 0.f;

    for (int kc = 0; kc < 4; kc++) {
        int c0 = kc * 48;
        for (int li = tid; li < 64*48; li += 192) {
            int t = li / 48, c = li - t*48;
            As[c*66 + t] = g_xi[(size_t)(t0 + t)*DI + c0 + c];
        }
        for (int li = tid; li < 48*48; li += 192) {
            int j = li / 48, c = li - j*48;
            Ws[c*50 + j] = (j < 38) ? xpw[j*DI + c0 + c] : 0.f;
        }
        __syncthreads();
#pragma unroll 4
        for (int c = 0; c < 48; c++) {
            float2 a01 = *(const float2*)&As[c*66 + tg*4];
            float2 a23 = *(const float2*)&As[c*66 + tg*4 + 2];
            float2 w01 = *(const float2*)&Ws[c*50 + jg*4];
            float2 w23 = *(const float2*)&Ws[c*50 + jg*4 + 2];
            acc[0][0] += a01.x*w01.x; acc[0][1] += a01.x*w01.y;
            acc[0][2] += a01.x*w23.x; acc[0][3] += a01.x*w23.y;
            acc[1][0] += a01.y*w01.x; acc[1][1] += a01.y*w01.y;
            acc[1][2] += a01.y*w23.x; acc[1][3] += a01.y*w23.y;
            acc[2][0] += a23.x*w01.x; acc[2][1] += a23.x*w01.y;
            acc[2][2] += a23.x*w23.x; acc[2][3] += a23.x*w23.y;
            acc[3][0] += a23.y*w01.x; acc[3][1] += a23.y*w01.y;
            acc[3][2] += a23.y*w23.x; acc[3][3] += a23.y*w23.y;
        }
        __syncthreads();
    }

    // aliases (mainloop reads are sync-fenced above)
    float* Xd = As;             // 64*42 = 2688 <= 3168
    float* Wd = Ws;             // 1344+192 = 1536 <= 2400
#pragma unroll
    for (int i = 0; i < 4; i++)
#pragma unroll
        for (int jj = 0; jj < 4; jj++) {
            int j = jg*4 + jj;
            if (j < 38) Xd[(tg*4 + i)*42 + j] = acc[i][jj];
        }
    for (int li = tid; li < DI*DTR; li += 192) Wd[li] = dpw[li];
    Wd[DI*DTR + tid] = dpb[tid];    // 192 threads == DI
    __syncthreads();

    for (int li = tid; li < 64*DS; li += 192) {
        int t = li >> 4, s = li & 15;
        g_Bm[(size_t)(t0 + t)*DS + s] = Xd[t*42 + DTR + s];
        g_Cm[(size_t)(t0 + t)*DS + s] = Xd[t*42 + DTR + DS + s];
    }
    for (int idx = tid; idx < 64*DI; idx += 192) {
        int tl2 = idx / DI;
        int d = idx - tl2*DI;
        float a = Wd[DI*DTR + d];
#pragma unroll
        for (int r = 0; r < DTR; r++) a += Xd[tl2*42 + r] * Wd[d*DTR + r];
        float sp = fmaxf(a, 0.f) + log1pf(__expf(-fabsf(a)));
        g_dt[(size_t)(t0 + tl2)*DI + d] = sp;
    }
}

// ======================================================================
// K3: scan pass A — local chunk scan, pipelined; stores h_end + dtsum.
// ======================================================================
__global__ __launch_bounds__(DI) void k_scanA(const float* __restrict__ A_log) {
    __shared__ float Bs[CSZ*DS];
    int d  = threadIdx.x;
    int b  = blockIdx.x >> 8;
    int ch = blockIdx.x & (NCH-1);
    int l0 = ch * CSZ;
    for (int li = d; li < CSZ*DS; li += DI)
        Bs[li] = g_Bm[(size_t)(b*LL + l0)*DS + li];
    __syncthreads();

    float Ad[DS], h[DS];
#pragma unroll
    for (int s = 0; s < DS; s++) { Ad[s] = -__expf(A_log[d*DS + s]); h[s] = 0.f; }
    float Ad0 = Ad[0];
    bool fast = true;
#pragma unroll
    for (int s = 1; s < DS; s++)
        fast = fast && (fabsf(Ad[s] - (s+1)*Ad0) <= 1e-4f * (float)(s+1) * fabsf(Ad0));

    float dtsum = 0.f;
    const float* dtp = g_dt + (size_t)(b*LL + l0)*DI + d;
    const float* xip = g_xi + (size_t)(b*LL + l0)*DI + d;

    float dtv = dtp[0];
    float xiv = xip[0];
    if (fast) {
#pragma unroll
        for (int t = 0; t < CSZ; t++) {
            float dtn = 0.f, xin = 0.f;
            if (t < CSZ-1) {
                dtn = dtp[(size_t)(t+1)*DI];
                xin = xip[(size_t)(t+1)*DI];
            }
            dtsum += dtv;
            float dx = dtv * xiv;
            float Ep[DS];
            build_pows(__expf(Ad0*dtv), Ep);
#pragma unroll
            for (int s = 0; s < DS; s++)
                h[s] = Ep[s] * h[s] + dx * Bs[t*DS + s];
            dtv = dtn; xiv = xin;
        }
    } else {
#pragma unroll
        for (int t = 0; t < CSZ; t++) {
            float dtn = 0.f, xin = 0.f;
            if (t < CSZ-1) {
                dtn = dtp[(size_t)(t+1)*DI];
                xin = xip[(size_t)(t+1)*DI];
            }
            dtsum += dtv;
            float dx = dtv * xiv;
#pragma unroll
            for (int s = 0; s < DS; s++)
                h[s] = __expf(Ad[s]*dtv) * h[s] + dx * Bs[t*DS + s];
            dtv = dtn; xiv = xin;
        }
    }
    size_t base = ((size_t)(b*NCH + ch)*DI + d)*DS;
    float4* pe = (float4*)(g_hend + base);
#pragma unroll
    for (int q = 0; q < 4; q++)
        pe[q] = make_float4(h[4*q], h[4*q+1], h[4*q+2], h[4*q+3]);
    g_dts[(size_t)(b*NCH + ch)*DI + d] = dtsum;
}

// ======================================================================
// K4a/b/c: parallel chunk combine.  P reconstructed as exp(Ad*dtsum).
// ======================================================================
__global__ __launch_bounds__(256) void k_scanB1(const float* __restrict__ A_log) {
    int r0 = blockIdx.x * 256 + threadIdx.x;   // row = d*DS + s
    int sc = blockIdx.y, b = blockIdx.z;
    float Ad = -__expf(A_log[r0]);
    int dd = r0 >> 4;
    size_t bh = ((size_t)(b*NCH) + sc*32)*ROWS + r0;
    size_t bd = ((size_t)(b*NCH) + sc*32)*DI + dd;
    float a = 1.f, bb = 0.f;
    float ds = g_dts[bd], hv = g_hend[bh];
#pragma unroll 4
    for (int c = 0; c < 32; c++) {
        float dsn = 0.f, hn = 0.f;
        if (c < 31) {
            dsn = g_dts[bd + (size_t)(c+1)*DI];
            hn  = g_hend[bh + (size_t)(c+1)*ROWS];
        }
        float P = __expf(Ad*ds);
        a = P*a;
        bb = P*bb + hv;
        ds = dsn; hv = hn;
    }
    size_t so = ((size_t)b*SUP + sc)*ROWS + r0;
    g_sP[so] = a;
    g_sH[so] = bb;
}

__global__ __launch_bounds__(256) void k_scanB2() {
    int idx = blockIdx.x * 256 + threadIdx.x;
    int b = idx / ROWS;
    int r = idx - b*ROWS;
    float H = 0.f;
#pragma unroll
    for (int sc = 0; sc < SUP; sc++) {
        size_t ofs = ((size_t)b*SUP + sc)*ROWS + r;
        g_sS[ofs] = H;
        H = g_sP[ofs]*H + g_sH[ofs];
    }
}

__global__ __launch_bounds__(256) void k_scanB3(const float* __restrict__ A_log) {
    int r0 = blockIdx.x * 256 + threadIdx.x;
    int sc = blockIdx.y, b = blockIdx.z;
    float Ad = -__expf(A_log[r0]);
    int dd = r0 >> 4;
    float H = g_sS[((size_t)b*SUP + sc)*ROWS + r0];
    size_t bh = ((size_t)(b*NCH) + sc*32)*ROWS + r0;
    size_t bd = ((size_t)(b*NCH) + sc*32)*DI + dd;
    float ds = g_dts[bd], hv = g_hend[bh];
#pragma unroll 4
    for (int c = 0; c < 32; c++) {
        float dsn = 0.f, hn = 0.f;
        if (c < 31) {
            dsn = g_dts[bd + (size_t)(c+1)*DI];
            hn  = g_hend[bh + (size_t)(c+1)*ROWS];
        }
        g_Hst[bh + (size_t)c*ROWS] = H;
        float P = __expf(Ad*ds);
        H = P*H + hv;
        ds = dsn; hv = hn;
    }
}

// ======================================================================
// K5: scan pass C — seeded re-scan + fused skip/gate, pipelined loads.
// ======================================================================
__global__ __launch_bounds__(DI) void k_scanC(const float* __restrict__ A_log,
                                              const float* __restrict__ Dp) {
    __shared__ float Bs[CSZ*DS];
    __shared__ float Cs[CSZ*DS];
    int d  = threadIdx.x;
    int b  = blockIdx.x >> 8;
    int ch = blockIdx.x & (NCH-1);
    int l0 = ch * CSZ;
    for (int li = d; li < CSZ*DS; li += DI) {
        Bs[li] = g_Bm[(size_t)(b*LL + l0)*DS + li];
        Cs[li] = g_Cm[(size_t)(b*LL + l0)*DS + li];
    }
    __syncthreads();

    float Ad[DS], h[DS];
#pragma unroll
    for (int s = 0; s < DS; s++) Ad[s] = -__expf(A_log[d*DS + s]);
    float Ad0 = Ad[0];
    bool fast = true;
#pragma unroll
    for (int s = 1; s < DS; s++)
        fast = fast && (fabsf(Ad[s] - (s+1)*Ad0) <= 1e-4f * (float)(s+1) * fabsf(Ad0));

    size_t hbase = ((size_t)(b*NCH + ch)*DI + d)*DS;
    const float4* hs = (const float4*)(g_Hst + hbase);
#pragma unroll
    for (int q = 0; q < 4; q++) {
        float4 v = hs[q];
        h[4*q] = v.x; h[4*q+1] = v.y; h[4*q+2] = v.z; h[4*q+3] = v.w;
    }
    float Dd = Dp[d];
    const float* dtp = g_dt + (size_t)(b*LL + l0)*DI + d;
    const float* xip = g_xi + (size_t)(b*LL + l0)*DI + d;
    const float* zp  = g_z  + (size_t)(b*LL + l0)*DI + d;
    float* outp      = g_ym + (size_t)(b*LL + l0)*DI + d;

    float dtv = dtp[0];
    float xiv = xip[0];
    float zv  = zp[0];
    if (fast) {
#pragma unroll
        for (int t = 0; t < CSZ; t++) {
            float dtn = 0.f, xin = 0.f, zn = 0.f;
            if (t < CSZ-1) {
                dtn = dtp[(size_t)(t+1)*DI];
                xin = xip[(size_t)(t+1)*DI];
                zn  = zp[(size_t)(t+1)*DI];
            }
            float dx = dtv * xiv;
            float Ep[DS];
            build_pows(__expf(Ad0*dtv), Ep);
            float y = 0.f;
#pragma unroll
            for (int s = 0; s < DS; s++) {
                h[s] = Ep[s]*h[s] + dx * Bs[t*DS + s];
                y += h[s] * Cs[t*DS + s];
            }
            float sz = zv / (1.f + __expf(-zv));
            outp[(size_t)t*DI] = (y + xiv*Dd) * sz;
            dtv = dtn; xiv = xin; zv = zn;
        }
    } else {
#pragma unroll
        for (int t = 0; t < CSZ; t++) {
            float dtn = 0.f, xin = 0.f, zn = 0.f;
            if (t < CSZ-1) {
                dtn = dtp[(size_t)(t+1)*DI];
                xin = xip[(size_t)(t+1)*DI];
                zn  = zp[(size_t)(t+1)*DI];
            }
            float dx = dtv * xiv;
            float y = 0.f;
#pragma unroll
            for (int s = 0; s < DS; s++) {
                h[s] = __expf(Ad[s]*dtv)*h[s] + dx * Bs[t*DS + s];
                y += h[s] * Cs[t*DS + s];
            }
            float sz = zv / (1.f + __expf(-zv));
            outp[(size_t)t*DI] = (y + xiv*Dd) * sz;
            dtv = dtn; xiv = xin; zv = zn;
        }
    }
}

// ======================================================================
// K6: out_proj GEMM (f32x2) -> [B, C, L]
// ======================================================================
__global__ __launch_bounds__(256) void k_outproj(const float* __restrict__ w) {
    __shared__ __align__(16) float As[64*66];
    __shared__ float Ws[64*49];
    int tid = threadIdx.x;
    int t0 = blockIdx.y * 64;
    int o0 = blockIdx.x * 48;
    int b  = t0 >> 12;
    int l0 = t0 & (LL-1);
    int tx = tid & 15, ty = tid >> 4;

    unsigned long long acc[2][3];
#pragma unroll
    for (int i = 0; i < 2; i++)
#pragma unroll
        for (int j = 0; j < 3; j++) acc[i][j] = 0ull;

    for (int ck = 0; ck < 3; ck++) {
        int c0 = ck * 64;
        for (int li = tid; li < 64*64; li += 256) {
            int tl = li >> 6, c = li & 63;
            As[c*66 + tl] = g_ym[(size_t)(t0 + tl)*DI + c0 + c];
        }
        for (int li = tid; li < 48*64; li += 256) {
            int ol = li >> 6, c = li & 63;
            Ws[c*49 + ol] = w[(o0 + ol)*DI + c0 + c];
        }
        __syncthreads();
#pragma unroll 8
        for (int c = 0; c < 64; c++) {
            unsigned long long a01 = *(const unsigned long long*)&As[c*66 + tx*4];
            unsigned long long a23 = *(const unsigned long long*)&As[c*66 + tx*4 + 2];
            float b0 = Ws[c*49 + ty*3 + 0];
            float b1 = Ws[c*49 + ty*3 + 1];
            float b2 = Ws[c*49 + ty*3 + 2];
            unsigned long long bd0 = pack2(b0, b0);
            unsigned long long bd1 = pack2(b1, b1);
            unsigned long long bd2 = pack2(b2, b2);
            ffma2(acc[0][0], a01, bd0); ffma2(acc[1][0], a23, bd0);
            ffma2(acc[0][1], a01, bd1); ffma2(acc[1][1], a23, bd1);
            ffma2(acc[0][2], a01, bd2); ffma2(acc[1][2], a23, bd2);
        }
        __syncthreads();
    }
#pragma unroll
    for (int j = 0; j < 3; j++) {
        int d = o0 + ty*3 + j;
        float2 lo = unpack2(acc[0][j]);
        float2 hi = unpack2(acc[1][j]);
        *(float4*)&g_xm[(size_t)(b*CCH + d)*LL + l0 + tx*4] = make_float4(lo.x, lo.y, hi.x, hi.y);
    }
}

// ======================================================================
// K7a: transpose conv2d weights -> g_wt[k=864][co=96]
// ======================================================================
__global__ __launch_bounds__(256) void k_wprep(const float* __restrict__ w) {
    int idx = blockIdx.x * 256 + threadIdx.x;   // < 864*96
    if (idx < KTOT*CCH) {
        int k = idx / CCH, co = idx - k*CCH;
        g_wt[idx] = w[(size_t)co*KTOT + k];
    }
}

// ======================================================================
// K7b: 3x3 conv via tf32 mma.sync (implicit GEMM) + BN + ReLU6 fused.
// Block 128 thr (4 warps).  Tile: co 16 x (4 rows x 64 px) = 16 x 256.
// grid (6 co-tiles, 16 y-tiles, 4 batch)
// ======================================================================
__global__ __launch_bounds__(128) void k_conv2d(
        const float* __restrict__ bng, const float* __restrict__ bnb,
        const float* __restrict__ bnm, const float* __restrict__ bnv,
        float* __restrict__ out) {
    __shared__ float Xs[8*6*66];     // 12.4 KB  [ci][row(y-1..y+4)][col(x+1)]
    __shared__ float Ws[72*16];      // 4.5 KB   [k_local][co]
    __shared__ int   offT[72];
    int tid = threadIdx.x;
    int lane = tid & 31, wid = tid >> 5;
    int co0 = blockIdx.x * 16;
    int y0  = blockIdx.y * 4;
    int b   = blockIdx.z;

    if (tid < 72) {
        int ci = tid / 9, r = tid - ci*9;
        offT[tid] = ci*396 + (r/3)*66 + (r - (r/3)*3);
    }
    // x-halo columns (0 and 65) are always outside the image -> zero once
    for (int li = tid; li < 96; li += 128) {
        int row = li >> 1, side = li & 1;
        Xs[row*66 + (side ? 65 : 0)] = 0.f;
    }

    float acc[8][4];
#pragma unroll
    for (int nt = 0; nt < 8; nt++)
#pragma unroll
        for (int q = 0; q < 4; q++) acc[nt][q] = 0.f;

    int arow = lane >> 2;      // co within tile (0..7)
    int kq   = lane & 3;       // k within 4

    for (int cc = 0; cc < 12; cc++) {
        int ci0 = cc * 8;
        __syncthreads();
        // interior fill: 48 rows x 16 float4
        for (int li = tid; li < 768; li += 128) {
            int row = li >> 4, q = li & 15;
            int ci = row / 6, yy = row - ci*6;
            int gy = y0 - 1 + yy;
            float4 v = make_float4(0.f, 0.f, 0.f, 0.f);
            if (gy >= 0 && gy < 64)
                v = *(const float4*)&g_xm[(((size_t)(b*CCH + ci0 + ci)*64 + gy)*64) + q*4];
            float* dp = Xs + row*66 + 1 + q*4;
            dp[0] = v.x; dp[1] = v.y; dp[2] = v.z; dp[3] = v.w;
        }
        // weights: Ws[k][co] from g_wt[(cc*72 + k)*96 + co0 + co]
        for (int li = tid; li < 72*16; li += 128) {
            int k = li >> 4, co = li & 15;
            Ws[li] = g_wt[(size_t)(cc*72 + k)*CCH + co0 + co];
        }
        __syncthreads();

#pragma unroll
        for (int kt = 0; kt < 9; kt++) {
            int k0 = kt*8 + kq;
            unsigned int a0 = to_tf32(Ws[(k0    )*16 + arow]);
            unsigned int a1 = to_tf32(Ws[(k0    )*16 + arow + 8]);
            unsigned int a2 = to_tf32(Ws[(k0 + 4)*16 + arow]);
            unsigned int a3 = to_tf32(Ws[(k0 + 4)*16 + arow + 8]);
            int off0 = offT[k0]     + wid*66;
            int off1 = offT[k0 + 4] + wid*66;
#pragma unroll
            for (int nt = 0; nt < 8; nt++) {
                int xq = nt*8 + (lane >> 2);
                unsigned int b0 = to_tf32(Xs[off0 + xq]);
                unsigned int b1 = to_tf32(Xs[off1 + xq]);
                asm volatile(
                    "mma.sync.aligned.m16n8k8.row.col.f32.tf32.tf32.f32 "
                    "{%0,%1,%2,%3}, {%4,%5,%6,%7}, {%8,%9}, {%0,%1,%2,%3};"
                    : "+f"(acc[nt][0]), "+f"(acc[nt][1]),
                      "+f"(acc[nt][2]), "+f"(acc[nt][3])
                    : "r"(a0), "r"(a1), "r"(a2), "r"(a3), "r"(b0), "r"(b1));
            }
        }
    }

    // epilogue: BN + ReLU6, store
    int c_lo = co0 + arow;
    int c_hi = c_lo + 8;
    float inv_lo = bng[c_lo] * rsqrtf(bnv[c_lo] + 1e-5f);
    float sh_lo  = bnb[c_lo] - bnm[c_lo]*inv_lo;
    float inv_hi = bng[c_hi] * rsqrtf(bnv[c_hi] + 1e-5f);
    float sh_hi  = bnb[c_hi] - bnm[c_hi]*inv_hi;
    int yrow = y0 + wid;
    int xb = (lane & 3)*2;
#pragma unroll
    for (int nt = 0; nt < 8; nt++) {
        int x = nt*8 + xb;
        float2 o0, o1;
        o0.x = fminf(fmaxf(acc[nt][0]*inv_lo + sh_lo, 0.f), 6.f);
        o0.y = fminf(fmaxf(acc[nt][1]*inv_lo + sh_lo, 0.f), 6.f);
        o1.x = fminf(fmaxf(acc[nt][2]*inv_hi + sh_hi, 0.f), 6.f);
        o1.y = fminf(fmaxf(acc[nt][3]*inv_hi + sh_hi, 0.f), 6.f);
        *(float2*)&out[((size_t)(b*CCH + c_lo)*64 + yrow)*64 + x] = o0;
        *(float2*)&out[((size_t)(b*CCH + c_hi)*64 + yrow)*64 + x] = o1;
    }
}

// ======================================================================
extern "C" void kernel_launch(void* const* d_in, const int* in_sizes, int n_in,
                              void* d_out, int out_size) {
    const float* x         = (const float*)d_in[0];
    const float* in_proj_w = (const float*)d_in[1];
    const float* conv1d_w  = (const float*)d_in[2];
    const float* conv1d_b  = (const float*)d_in[3];
    const float* x_proj_w  = (const float*)d_in[4];
    const float* dt_proj_w = (const float*)d_in[5];
    const float* dt_proj_b = (const float*)d_in[6];
    const float* A_log     = (const float*)d_in[7];
    const float* Dp        = (const float*)d_in[8];
    const float* out_proj_w= (const float*)d_in[9];
    const float* conv2d_w  = (const float*)d_in[10];
    const float* bn_g      = (const float*)d_in[11];
    const float* bn_b      = (const float*)d_in[12];
    const float* bn_m      = (const float*)d_in[13];
    const float* bn_v      = (const float*)d_in[14];
    float* out = (float*)d_out;

    k_wprep  <<<(KTOT*CCH + 255)/256, 256>>>(conv2d_w);
    k_inproj <<<dim3(6, 256), 256>>>(x, in_proj_w);
    k_conv1d <<<(NTOK/8)*48/256, 256>>>(conv1d_w, conv1d_b);
    k_xproj  <<<NTOK/64, 192>>>(x_proj_w, dt_proj_w, dt_proj_b);
    k_scanA  <<<BB*NCH, DI>>>(A_log);
    k_scanB1 <<<dim3(12, SUP, BB), 256>>>(A_log);
    k_scanB2 <<<BB*ROWS/256, 256>>>();
    k_scanB3 <<<dim3(12, SUP, BB), 256>>>(A_log);
    k_scanC  <<<BB*NCH, DI>>>(A_log, Dp);
    k_outproj<<<dim3(2, 256), 256>>>(out_proj_w);
    k_conv2d <<<dim3(6, 16, 4), 128>>>(bn_g, bn_b, bn_m, bn_v, out);
}